// round 6
// baseline (speedup 1.0000x reference)
#include <cuda_runtime.h>
#include <math.h>
#include <float.h>

#define T_    4
#define C_    64
#define WW    96
#define HW    9216
#define CI    16
#define PS    7
#define WS    21
#define NQX   24
#define NQ    576
#define NC    441
#define KSEL  100
#define SCALE 10.0f
#define RGN   27
#define RGN2  729
#define NT    256
#define NTS   384
#define B1P   56
#define QST   (RGN*WS)      // 567

// smem layout (float offsets)
#define SM_B1   0            // 896
#define SM_RG   896          // 11664
#define SM_Q    12560        // 3970
#define SM_QB   16530        // 3970
#define SM_SRT  20500        // u64[512] = 1024 floats
#define SM_W    21524        // 104
#define SM_CID  21628        // 100
#define SM_RO   21728        // 147
#define SM_CO   21875        // 147
#define SM_GOFF 22022        // 729
#define SM_TOT  22751        // 91004 bytes

typedef unsigned long long ull;

// scratch (gmem layouts: b1 interleaved [t][pix][16]; b3+b2 fused [t][pix][32])
__device__ float g_b1i[(size_t)T_*HW*CI];
__device__ float g_b32[(size_t)T_*HW*32];
__device__ float g_acc[T_*CI*HW];
__device__ float g_Z[HW];

__device__ __forceinline__ int clipi(int v){ return min(max(v,0),95); }
__device__ __forceinline__ unsigned ordf(float f){
    unsigned b = __float_as_uint(f);
    return (b & 0x80000000u) ? ~b : (b | 0x80000000u);
}
__device__ __forceinline__ float iordf(unsigned u){
    unsigned b = (u & 0x80000000u) ? (u & 0x7FFFFFFFu) : ~u;
    return __uint_as_float(b);
}
__device__ __forceinline__ ull pack2(float lo, float hi){
    ull r; asm("mov.b64 %0, {%1, %2};" : "=l"(r) : "f"(lo), "f"(hi)); return r;
}
__device__ __forceinline__ void fma2(ull &acc, ull a, ull b){
    asm("fma.rn.f32x2 %0, %1, %2, %0;" : "+l"(acc) : "l"(a), "l"(b));
}
__device__ __forceinline__ float sum2(ull v){
    return __uint_as_float((unsigned)v) + __uint_as_float((unsigned)(v>>32));
}

// ---------------------------------------------------------------- zero
__global__ void k_zero(){
    int i = blockIdx.x*NT + threadIdx.x;
    if (i < T_*CI*HW) g_acc[i] = 0.f;
    if (i < HW)       g_Z[i]   = 0.f;
}

// ---------------------------------------------------------------- Z counts
__global__ void k_zcount(){
    int q  = blockIdx.x;
    int a  = threadIdx.x / PS, b = threadIdx.x % PS;
    int qi = (q / NQX)*4, qj = (q % NQX)*4;
    atomicAdd(&g_Z[min(qi+a,95)*WW + min(qj+b,95)], 1.0f);
}

// ---------------------------------------------------------------- fused 3x conv1x1 (interleaved outputs)
__global__ void k_proj(const float* __restrict__ vid,
                       const float* __restrict__ gw, const float* __restrict__ gb,
                       const float* __restrict__ tw, const float* __restrict__ tb,
                       const float* __restrict__ pw, const float* __restrict__ pb){
    __shared__ float sw[3*CI*C_ + 3*CI];
    for (int i=threadIdx.x; i<CI*C_; i+=NT){
        sw[i]          = gw[i];
        sw[CI*C_+i]    = tw[i];
        sw[2*CI*C_+i]  = pw[i];
    }
    if (threadIdx.x < CI){
        sw[3*CI*C_         + threadIdx.x] = gb[threadIdx.x];
        sw[3*CI*C_ +   CI  + threadIdx.x] = tb[threadIdx.x];
        sw[3*CI*C_ + 2*CI  + threadIdx.x] = pb[threadIdx.x];
    }
    __syncthreads();

    int gid = blockIdx.x*NT + threadIdx.x;   // t*HW + pix
    int t = gid / HW, pix = gid % HW;

    float a1[CI], a2[CI], a3[CI];
    #pragma unroll
    for (int o=0;o<CI;o++){
        a1[o] = sw[3*CI*C_ + o];
        a2[o] = sw[3*CI*C_ + CI + o];
        a3[o] = sw[3*CI*C_ + 2*CI + o];
    }
    const float* vp = vid + (size_t)t*C_*HW + pix;
    for (int c=0;c<C_;c++){
        float v = vp[c*HW];
        #pragma unroll
        for (int o=0;o<CI;o++){
            a1[o] += v*sw[o*C_+c];
            a2[o] += v*sw[CI*C_ + o*C_+c];
            a3[o] += v*sw[2*CI*C_ + o*C_+c];
        }
    }
    // b1 interleaved [gid][16]
    float4* o1 = (float4*)g_b1i + (size_t)gid*4;
    #pragma unroll
    for (int c=0;c<4;c++) o1[c] = make_float4(a1[4*c],a1[4*c+1],a1[4*c+2],a1[4*c+3]);
    // fused [gid][b3:16, b2:16]
    float4* o32 = (float4*)g_b32 + (size_t)gid*8;
    #pragma unroll
    for (int c=0;c<4;c++) o32[c]   = make_float4(a3[4*c],a3[4*c+1],a3[4*c+2],a3[4*c+3]);
    #pragma unroll
    for (int c=0;c<4;c++) o32[4+c] = make_float4(a2[4*c],a2[4*c+1],a2[4*c+2],a2[4*c+3]);
}

// ---------------------------------------------------------------- main kernel
__global__ void __launch_bounds__(NTS, 2) k_score(){
    extern __shared__ float sm[];
    float* s_b1 = sm + SM_B1;
    float* s_rg = sm + SM_RG;
    float4* s_rg4 = (float4*)(sm + SM_RG);   // b2 interleaved layout (aliases s_rg)
    float* s_Q  = sm + SM_Q;
    float* s_QB = sm + SM_QB;
    ull*   s_srt = (ull*)(sm + SM_SRT);
    float* s_w   = sm + SM_W;
    int*   s_cid = (int*)(sm + SM_CID);
    int*   s_ro  = (int*)(sm + SM_RO);
    int*   s_co  = (int*)(sm + SM_CO);
    int*   s_goff= (int*)(sm + SM_GOFF);
    int*   s_offT= (int*)s_Q;    // alias Q/QB (dead after softmax)

    int blk = blockIdx.x;
    int t = blk / NQ, q = blk % NQ;
    int qi = (q / NQX)*4, qj = (q % NQX)*4;
    int tid = threadIdx.x;

    int rmin = max(qi-10, 0), cmin = max(qj-10, 0);
    bool colAffine = (qj >= 12 && qj <= 76);

    // ---- tables
    if (tid < 147){
        int d_ = tid/7, e_ = tid%7;
        s_ro[tid] = min(clipi(qi + d_ - 10) + e_, 95) - rmin;
        s_co[tid] = min(clipi(qj + d_ - 10) + e_, 95) - cmin;
    }
    for (int i=tid; i<RGN2; i+=NTS){
        int rr = i/RGN, cc = i - rr*RGN;
        s_goff[i] = min(rmin+rr,95)*WW + min(cmin+cc,95);
    }
    // b1 patch: 4 LDG.128 per pixel, scatter into pair-layout s_b1[ci][a*8+b]
    if (tid < 49){
        int a = tid/7, b = tid - 7*a;
        int pp = min(qi+a,95)*WW + min(qj+b,95);
        const float4* b1p = (const float4*)g_b1i + ((size_t)t*HW + pp)*4;
        #pragma unroll
        for (int c=0;c<4;c++){
            float4 v = b1p[c];
            s_b1[(4*c+0)*B1P + a*8 + b] = v.x;
            s_b1[(4*c+1)*B1P + a*8 + b] = v.y;
            s_b1[(4*c+2)*B1P + a*8 + b] = v.z;
            s_b1[(4*c+3)*B1P + a*8 + b] = v.w;
        }
    }
    if (tid >= 64 && tid < 64+CI*7){
        int u = tid - 64, ci = u/7, a = u - 7*ci;
        s_b1[ci*B1P + a*8 + 7] = 0.f;
    }
    __syncthreads();

    // ---- region load: one fused sweep, 8 LDG.128 per pixel
    //      b3 -> planar smem (register transpose), b2 -> registers
    const float4* r4 = (const float4*)g_b32 + (size_t)t*HW*8;
    float4 vb4a[4], vb4b[4];
    {
        int go0 = s_goff[tid];
        const float4* p0 = r4 + (size_t)go0*8;
        float4 x0=p0[0], x1=p0[1], x2=p0[2], x3=p0[3];
        s_rg[ 0*RGN2+tid]=x0.x; s_rg[ 1*RGN2+tid]=x0.y; s_rg[ 2*RGN2+tid]=x0.z; s_rg[ 3*RGN2+tid]=x0.w;
        s_rg[ 4*RGN2+tid]=x1.x; s_rg[ 5*RGN2+tid]=x1.y; s_rg[ 6*RGN2+tid]=x1.z; s_rg[ 7*RGN2+tid]=x1.w;
        s_rg[ 8*RGN2+tid]=x2.x; s_rg[ 9*RGN2+tid]=x2.y; s_rg[10*RGN2+tid]=x2.z; s_rg[11*RGN2+tid]=x2.w;
        s_rg[12*RGN2+tid]=x3.x; s_rg[13*RGN2+tid]=x3.y; s_rg[14*RGN2+tid]=x3.z; s_rg[15*RGN2+tid]=x3.w;
        vb4a[0]=p0[4]; vb4a[1]=p0[5]; vb4a[2]=p0[6]; vb4a[3]=p0[7];
        if (tid + NTS < RGN2){
            int go1 = s_goff[tid+NTS];
            const float4* p1 = r4 + (size_t)go1*8;
            float4 y0=p1[0], y1=p1[1], y2=p1[2], y3=p1[3];
            s_rg[ 0*RGN2+tid+NTS]=y0.x; s_rg[ 1*RGN2+tid+NTS]=y0.y; s_rg[ 2*RGN2+tid+NTS]=y0.z; s_rg[ 3*RGN2+tid+NTS]=y0.w;
            s_rg[ 4*RGN2+tid+NTS]=y1.x; s_rg[ 5*RGN2+tid+NTS]=y1.y; s_rg[ 6*RGN2+tid+NTS]=y1.z; s_rg[ 7*RGN2+tid+NTS]=y1.w;
            s_rg[ 8*RGN2+tid+NTS]=y2.x; s_rg[ 9*RGN2+tid+NTS]=y2.y; s_rg[10*RGN2+tid+NTS]=y2.z; s_rg[11*RGN2+tid+NTS]=y2.w;
            s_rg[12*RGN2+tid+NTS]=y3.x; s_rg[13*RGN2+tid+NTS]=y3.y; s_rg[14*RGN2+tid+NTS]=y3.z; s_rg[15*RGN2+tid+NTS]=y3.w;
            vb4b[0]=p1[4]; vb4b[1]=p1[5]; vb4b[2]=p1[6]; vb4b[3]=p1[7];
        }
    }
    __syncthreads();

    // ---- stage 1 (split over ci halves): Q[a][r][dj] via f32x2
    {
        int tid1 = (tid < 192) ? tid : tid - 192;
        int ci0  = (tid < 192) ? 0 : 8;
        float* Qp = (tid < 192) ? s_Q : s_QB;
        if (tid1 < 189){
            int r = tid1/7, dj0 = (tid1%7)*3;
            ull acc2[7][3];
            #pragma unroll
            for (int a=0;a<7;a++){ acc2[a][0]=0ull; acc2[a][1]=0ull; acc2[a][2]=0ull; }

            if (colAffine){
                for (int cc=0; cc<8; cc++){
                    int ci = ci0 + cc;
                    const float* row = s_rg + ci*RGN2 + r*RGN + dj0;
                    float win[9];
                    #pragma unroll
                    for (int j=0;j<9;j++) win[j] = row[j];
                    ull wp[9];
                    #pragma unroll
                    for (int b=0;b<8;b++) wp[b] = pack2(win[b], win[b+1]);
                    wp[8] = pack2(win[8], 0.f);
                    const ulonglong2* wq2 = (const ulonglong2*)(s_b1 + ci*B1P);
                    #pragma unroll
                    for (int a=0;a<7;a++){
                        ulonglong2 wab = wq2[a*2], wcd = wq2[a*2+1];
                        ull w01 = wab.x, w23 = wab.y, w45 = wcd.x, w67 = wcd.y;
                        #pragma unroll
                        for (int k=0;k<3;k++){
                            fma2(acc2[a][k], w01, wp[k]);
                            fma2(acc2[a][k], w23, wp[k+2]);
                            fma2(acc2[a][k], w45, wp[k+4]);
                            fma2(acc2[a][k], w67, wp[k+6]);
                        }
                    }
                }
            } else {
                int clim = 95 - cmin;
                int cb[3];
                #pragma unroll
                for (int k=0;k<3;k++) cb[k] = s_co[(dj0+k)*7];
                for (int cc=0; cc<8; cc++){
                    int ci = ci0 + cc;
                    const float* row = s_rg + ci*RGN2 + r*RGN;
                    ull vp[3][4];
                    #pragma unroll
                    for (int k=0;k<3;k++){
                        float w0=row[min(cb[k]+0,clim)], w1=row[min(cb[k]+1,clim)];
                        float w2=row[min(cb[k]+2,clim)], w3=row[min(cb[k]+3,clim)];
                        float w4=row[min(cb[k]+4,clim)], w5=row[min(cb[k]+5,clim)];
                        float w6=row[min(cb[k]+6,clim)], w7=row[min(cb[k]+7,clim)];
                        vp[k][0]=pack2(w0,w1); vp[k][1]=pack2(w2,w3);
                        vp[k][2]=pack2(w4,w5); vp[k][3]=pack2(w6,w7);
                    }
                    const ulonglong2* wq2 = (const ulonglong2*)(s_b1 + ci*B1P);
                    #pragma unroll
                    for (int a=0;a<7;a++){
                        ulonglong2 wab = wq2[a*2], wcd = wq2[a*2+1];
                        ull w01 = wab.x, w23 = wab.y, w45 = wcd.x, w67 = wcd.y;
                        #pragma unroll
                        for (int k=0;k<3;k++){
                            fma2(acc2[a][k], w01, vp[k][0]);
                            fma2(acc2[a][k], w23, vp[k][1]);
                            fma2(acc2[a][k], w45, vp[k][2]);
                            fma2(acc2[a][k], w67, vp[k][3]);
                        }
                    }
                }
            }
            #pragma unroll
            for (int a=0;a<7;a++)
                #pragma unroll
                for (int k=0;k<3;k++)
                    Qp[a*QST + r*WS + dj0 + k] = sum2(acc2[a][k]);
        }
    }
    __syncthreads();

    // ---- stage 2: scores (sum both ci-halves) -> packed sort keys
    for (int c=tid; c<512; c+=NTS){
        ull key = 0ull;
        if (c < NC){
            int di = c/WS, dj = c - WS*di;
            float sc = 0.f;
            #pragma unroll
            for (int a=0;a<7;a++){
                int qo = a*QST + s_ro[di*7+a]*WS + dj;
                sc += s_Q[qo] + s_QB[qo];
            }
            key = ((ull)ordf(sc) << 32) | (unsigned)c;
        }
        s_srt[c] = key;
    }

    // ---- bitonic sort 512 u64 descending (first 256 threads work; all sync)
    for (int k=2; k<=512; k<<=1){
        for (int j=k>>1; j>0; j>>=1){
            __syncthreads();
            if (tid < 256){
                int lo = tid & (j-1);
                int i0 = ((tid & ~(j-1))<<1) | lo;
                int i1 = i0 | j;
                bool desc = (i0 & k) == 0;
                ull k0 = s_srt[i0], k1 = s_srt[i1];
                if ((k0 < k1) == desc){ s_srt[i0]=k1; s_srt[i1]=k0; }
            }
        }
    }
    __syncthreads();

    // ---- softmax over top-100
    {
        float maxs = iordf((unsigned)(s_srt[0] >> 32));
        if (tid < KSEL){
            ull key = s_srt[tid];
            float sc = iordf((unsigned)(key >> 32));
            s_w[tid]   = expf((sc - maxs)*SCALE);
            s_cid[tid] = (int)(key & 0x1FFu);
        }
        __syncthreads();
        if (tid < 32){
            float s = 0.f;
            for (int k=tid; k<KSEL; k+=32) s += s_w[k];
            #pragma unroll
            for (int o=16;o;o>>=1) s += __shfl_xor_sync(0xffffffffu, s, o);
            if (tid == 0) s_w[KSEL] = 1.f/s;
        }
        __syncthreads();
        if (tid < KSEL) s_w[tid] *= s_w[KSEL];
    }

    // ---- commit prefetched b2 in ci-interleaved float4 layout + offset table
    #pragma unroll
    for (int g=0; g<4; g++)
        s_rg4[g*RGN2 + tid] = vb4a[g];
    if (tid + NTS < RGN2){
        #pragma unroll
        for (int g=0; g<4; g++)
            s_rg4[g*RGN2 + tid + NTS] = vb4b[g];
    }
    for (int i=tid; i<KSEL*49; i+=NTS){
        int k = i/49, p = i - 49*k;
        int c = s_cid[k];
        int pa = p/7, pb = p - 7*pa;
        s_offT[p*100 + k] = s_ro[(c/WS)*7 + pa]*RGN + s_co[(c%WS)*7 + pb];
    }
    __syncthreads();

    // ---- aggregation: 196 threads, 1 LDS.128 gather per (k, cig)
    if (tid < 196){
        int p   = tid % 49;
        int cig = tid / 49;
        const float4* rg = s_rg4 + cig*RGN2;
        const int*   offp = s_offT + p*100;
        float a0=0.f, a1=0.f, a2=0.f, a3=0.f;
        #pragma unroll
        for (int k=0; k<KSEL; k+=4){
            int4   o4 = *(const int4*)  (offp + k);
            float4 w4 = *(const float4*)(s_w + k);
            float4 v0 = rg[o4.x], v1 = rg[o4.y], v2 = rg[o4.z], v3 = rg[o4.w];
            a0 += w4.x*v0.x; a1 += w4.x*v0.y; a2 += w4.x*v0.z; a3 += w4.x*v0.w;
            a0 += w4.y*v1.x; a1 += w4.y*v1.y; a2 += w4.y*v1.z; a3 += w4.y*v1.w;
            a0 += w4.z*v2.x; a1 += w4.z*v2.y; a2 += w4.z*v2.z; a3 += w4.z*v2.w;
            a0 += w4.w*v3.x; a1 += w4.w*v3.y; a2 += w4.w*v3.z; a3 += w4.w*v3.w;
        }
        int pa = p/7, pb = p - 7*pa;
        int pix = min(qi+pa,95)*WW + min(qj+pb,95);
        float* accb = g_acc + (size_t)(t*CI + cig*4)*HW + pix;
        atomicAdd(accb,        a0);
        atomicAdd(accb +   HW, a1);
        atomicAdd(accb + 2*HW, a2);
        atomicAdd(accb + 3*HW, a3);
    }
}

// ---------------------------------------------------------------- y = acc/Z ; out = vid + conv1x1(y)
__global__ void k_final(const float* __restrict__ vid, const float* __restrict__ Ww,
                        const float* __restrict__ Wb, float* __restrict__ out){
    __shared__ float sw[C_*CI + C_];
    for (int i=threadIdx.x; i<C_*CI; i+=NT) sw[i] = Ww[i];
    if (threadIdx.x < C_) sw[C_*CI+threadIdx.x] = Wb[threadIdx.x];
    __syncthreads();

    int gid = blockIdx.x*NT + threadIdx.x;
    int t = gid / HW, pix = gid % HW;

    float inv = 1.f / g_Z[pix];
    float y[CI];
    #pragma unroll
    for (int ci=0;ci<CI;ci++) y[ci] = g_acc[(t*CI+ci)*HW + pix]*inv;

    const float* vp = vid + (size_t)t*C_*HW + pix;
    float*       op = out + (size_t)t*C_*HW + pix;
    for (int co=0;co<C_;co++){
        float s = sw[C_*CI+co];
        #pragma unroll
        for (int ci=0;ci<CI;ci++) s += sw[co*CI+ci]*y[ci];
        op[co*HW] = vp[co*HW] + s;
    }
}

// ---------------------------------------------------------------- launch
extern "C" void kernel_launch(void* const* d_in, const int* in_sizes, int n_in,
                              void* d_out, int out_size){
    const float* vid  = (const float*)d_in[0];
    const float* g_w  = (const float*)d_in[1];
    const float* g_b  = (const float*)d_in[2];
    const float* th_w = (const float*)d_in[3];
    const float* th_b = (const float*)d_in[4];
    const float* ph_w = (const float*)d_in[5];
    const float* ph_b = (const float*)d_in[6];
    const float* W_w  = (const float*)d_in[7];
    const float* W_b  = (const float*)d_in[8];
    float* out = (float*)d_out;

    const int SMEM = SM_TOT * 4;   // 91004 B
    cudaFuncSetAttribute(k_score, cudaFuncAttributeMaxDynamicSharedMemorySize, SMEM);

    k_zero  <<<(T_*CI*HW + NT-1)/NT, NT>>>();
    k_proj  <<<T_*HW/NT, NT>>>(vid, g_w, g_b, th_w, th_b, ph_w, ph_b);
    k_zcount<<<NQ, PS*PS>>>();
    k_score <<<T_*NQ, NTS, SMEM>>>();
    k_final <<<T_*HW/NT, NT>>>(vid, W_w, W_b, out);
}

// round 7
// speedup vs baseline: 1.2509x; 1.2509x over previous
#include <cuda_runtime.h>
#include <math.h>
#include <float.h>

#define T_    4
#define C_    64
#define WW    96
#define HW    9216
#define CI    16
#define PS    7
#define WS    21
#define NQX   24
#define NQ    576
#define NC    441
#define KSEL  100
#define SCALE 10.0f
#define RGN   27
#define RGN2  729
#define NT    256
#define B1P   56
#define QST   (RGN*WS)      // 567

// smem layout (float offsets)
#define SM_B1   0            // 896
#define SM_RG   896          // 11664 (16B aligned: 896*4=3584)
#define SM_Q    12560        // 3970  (sort buffer B + s_off alias here)
#define SM_SRT  16530        // u64[512] = 1024 floats (sort buffer A)
#define SM_W    17556        // 104
#define SM_CID  17660        // 100
#define SM_RO   17760        // 147
#define SM_CO   17907        // 147
#define SM_GOFF 18054        // 729
#define SM_TOT  18783        // 75132 bytes

typedef unsigned long long ull;

// scratch (planar layouts)
__device__ float g_b1[T_*CI*HW];
__device__ float g_b2[T_*CI*HW];
__device__ float g_b3[T_*CI*HW];
__device__ float g_acc[T_*CI*HW];
__device__ float g_Z[HW];

__device__ __forceinline__ int clipi(int v){ return min(max(v,0),95); }
__device__ __forceinline__ unsigned ordf(float f){
    unsigned b = __float_as_uint(f);
    return (b & 0x80000000u) ? ~b : (b | 0x80000000u);
}
__device__ __forceinline__ float iordf(unsigned u){
    unsigned b = (u & 0x80000000u) ? (u & 0x7FFFFFFFu) : ~u;
    return __uint_as_float(b);
}
__device__ __forceinline__ ull pack2(float lo, float hi){
    ull r; asm("mov.b64 %0, {%1, %2};" : "=l"(r) : "f"(lo), "f"(hi)); return r;
}
__device__ __forceinline__ void fma2(ull &acc, ull a, ull b){
    asm("fma.rn.f32x2 %0, %1, %2, %0;" : "+l"(acc) : "l"(a), "l"(b));
}
__device__ __forceinline__ float sum2(ull v){
    return __uint_as_float((unsigned)v) + __uint_as_float((unsigned)(v>>32));
}
// bitonic compare-exchange via shuffle: element value v at position p
__device__ __forceinline__ ull cmpshfl(ull v, int p, int j, int k){
    ull o = __shfl_xor_sync(0xffffffffu, v, j);
    bool keepMax = (((p & j)==0) == ((p & k)==0));
    ull mx = v > o ? v : o, mn = v > o ? o : v;
    return keepMax ? mx : mn;
}

// ---------------------------------------------------------------- zero
__global__ void k_zero(){
    int i = blockIdx.x*NT + threadIdx.x;
    if (i < T_*CI*HW) g_acc[i] = 0.f;
    if (i < HW)       g_Z[i]   = 0.f;
}

// ---------------------------------------------------------------- Z counts
__global__ void k_zcount(){
    int q  = blockIdx.x;
    int a  = threadIdx.x / PS, b = threadIdx.x % PS;
    int qi = (q / NQX)*4, qj = (q % NQX)*4;
    atomicAdd(&g_Z[min(qi+a,95)*WW + min(qj+b,95)], 1.0f);
}

// ---------------------------------------------------------------- fused 3x conv1x1
__global__ void k_proj(const float* __restrict__ vid,
                       const float* __restrict__ gw, const float* __restrict__ gb,
                       const float* __restrict__ tw, const float* __restrict__ tb,
                       const float* __restrict__ pw, const float* __restrict__ pb){
    __shared__ float sw[3*CI*C_ + 3*CI];
    for (int i=threadIdx.x; i<CI*C_; i+=NT){
        sw[i]          = gw[i];
        sw[CI*C_+i]    = tw[i];
        sw[2*CI*C_+i]  = pw[i];
    }
    if (threadIdx.x < CI){
        sw[3*CI*C_         + threadIdx.x] = gb[threadIdx.x];
        sw[3*CI*C_ +   CI  + threadIdx.x] = tb[threadIdx.x];
        sw[3*CI*C_ + 2*CI  + threadIdx.x] = pb[threadIdx.x];
    }
    __syncthreads();

    int gid = blockIdx.x*NT + threadIdx.x;
    int t = gid / HW, pix = gid % HW;

    float a1[CI], a2[CI], a3[CI];
    #pragma unroll
    for (int o=0;o<CI;o++){
        a1[o] = sw[3*CI*C_ + o];
        a2[o] = sw[3*CI*C_ + CI + o];
        a3[o] = sw[3*CI*C_ + 2*CI + o];
    }
    const float* vp = vid + (size_t)t*C_*HW + pix;
    for (int c=0;c<C_;c++){
        float v = vp[c*HW];
        #pragma unroll
        for (int o=0;o<CI;o++){
            a1[o] += v*sw[o*C_+c];
            a2[o] += v*sw[CI*C_ + o*C_+c];
            a3[o] += v*sw[2*CI*C_ + o*C_+c];
        }
    }
    float* o1 = g_b1 + (size_t)t*CI*HW + pix;
    float* o2 = g_b2 + (size_t)t*CI*HW + pix;
    float* o3 = g_b3 + (size_t)t*CI*HW + pix;
    #pragma unroll
    for (int o=0;o<CI;o++){ o1[o*HW]=a1[o]; o2[o*HW]=a2[o]; o3[o*HW]=a3[o]; }
}

// ---------------------------------------------------------------- main kernel
__global__ void __launch_bounds__(NT, 3) k_score(){
    extern __shared__ float sm[];
    float* s_b1 = sm + SM_B1;
    float* s_rg = sm + SM_RG;
    float4* s_rg4 = (float4*)(sm + SM_RG);    // b2 interleaved (aliases s_rg)
    float* s_Q  = sm + SM_Q;
    ull*   s_srt = (ull*)(sm + SM_SRT);       // sort buffer A + final top-100
    ull*   s_bufB = (ull*)(sm + SM_Q);        // sort buffer B (Q dead during sort)
    float* s_w   = sm + SM_W;
    int*   s_cid = (int*)(sm + SM_CID);
    int*   s_ro  = (int*)(sm + SM_RO);
    int*   s_co  = (int*)(sm + SM_CO);
    int*   s_goff= (int*)(sm + SM_GOFF);
    int*   s_off = (int*)s_Q;                 // [k][49] table, built after sort

    int blk = blockIdx.x;
    int t = blk / NQ, q = blk % NQ;
    int qi = (q / NQX)*4, qj = (q % NQX)*4;
    int tid = threadIdx.x;

    int rmin = max(qi-10, 0), cmin = max(qj-10, 0);
    bool colAffine = (qj >= 12 && qj <= 76);

    // ---- tables
    if (tid < 147){
        int d_ = tid/7, e_ = tid%7;
        s_ro[tid] = min(clipi(qi + d_ - 10) + e_, 95) - rmin;
        s_co[tid] = min(clipi(qj + d_ - 10) + e_, 95) - cmin;
    }
    for (int i=tid; i<RGN2; i+=NT){
        int rr = i/RGN, cc = i - rr*RGN;
        s_goff[i] = min(rmin+rr,95)*WW + min(cmin+cc,95);
    }
    const float* b1t = g_b1 + (size_t)t*CI*HW;
    for (int i=tid; i<CI*49; i+=NT){
        int ci = i/49, rem = i - 49*ci, a = rem/7, b = rem - 7*a;
        s_b1[ci*B1P + a*8 + b] = b1t[ci*HW + min(qi+a,95)*WW + min(qj+b,95)];
    }
    if (tid < CI*7){
        int ci = tid/7, a = tid - 7*ci;
        s_b1[ci*B1P + a*8 + 7] = 0.f;
    }
    __syncthreads();

    // ---- load b3 region (planar): 1 goff LDS feeds 16 coalesced LDG
    {
        const float* b3t = g_b3 + (size_t)t*CI*HW;
        for (int i=tid; i<RGN2; i+=NT){
            int go = s_goff[i];
            #pragma unroll
            for (int ci=0;ci<CI;ci++) s_rg[ci*RGN2+i] = b3t[ci*HW+go];
        }
    }
    __syncthreads();

    // ---- stage 1: Q[a][r][dj] via f32x2, weights via LDS.128
    if (tid < 189){
        int r = tid/7, dj0 = (tid%7)*3;
        ull acc2[7][3];
        #pragma unroll
        for (int a=0;a<7;a++){ acc2[a][0]=0ull; acc2[a][1]=0ull; acc2[a][2]=0ull; }

        if (colAffine){
            for (int ci=0; ci<CI; ci++){
                const float* row = s_rg + ci*RGN2 + r*RGN + dj0;
                float win[9];
                #pragma unroll
                for (int j=0;j<9;j++) win[j] = row[j];
                ull wp[9];
                #pragma unroll
                for (int b=0;b<8;b++) wp[b] = pack2(win[b], win[b+1]);
                wp[8] = pack2(win[8], 0.f);
                const ulonglong2* wq2 = (const ulonglong2*)(s_b1 + ci*B1P);
                #pragma unroll
                for (int a=0;a<7;a++){
                    ulonglong2 wab = wq2[a*2], wcd = wq2[a*2+1];
                    #pragma unroll
                    for (int k=0;k<3;k++){
                        fma2(acc2[a][k], wab.x, wp[k]);
                        fma2(acc2[a][k], wab.y, wp[k+2]);
                        fma2(acc2[a][k], wcd.x, wp[k+4]);
                        fma2(acc2[a][k], wcd.y, wp[k+6]);
                    }
                }
            }
        } else {
            int clim = 95 - cmin;
            int cb[3];
            #pragma unroll
            for (int k=0;k<3;k++) cb[k] = s_co[(dj0+k)*7];
            for (int ci=0; ci<CI; ci++){
                const float* row = s_rg + ci*RGN2 + r*RGN;
                ull vp[3][4];
                #pragma unroll
                for (int k=0;k<3;k++){
                    float w0=row[min(cb[k]+0,clim)], w1=row[min(cb[k]+1,clim)];
                    float w2=row[min(cb[k]+2,clim)], w3=row[min(cb[k]+3,clim)];
                    float w4=row[min(cb[k]+4,clim)], w5=row[min(cb[k]+5,clim)];
                    float w6=row[min(cb[k]+6,clim)], w7=row[min(cb[k]+7,clim)];
                    vp[k][0]=pack2(w0,w1); vp[k][1]=pack2(w2,w3);
                    vp[k][2]=pack2(w4,w5); vp[k][3]=pack2(w6,w7);
                }
                const ulonglong2* wq2 = (const ulonglong2*)(s_b1 + ci*B1P);
                #pragma unroll
                for (int a=0;a<7;a++){
                    ulonglong2 wab = wq2[a*2], wcd = wq2[a*2+1];
                    #pragma unroll
                    for (int k=0;k<3;k++){
                        fma2(acc2[a][k], wab.x, vp[k][0]);
                        fma2(acc2[a][k], wab.y, vp[k][1]);
                        fma2(acc2[a][k], wcd.x, vp[k][2]);
                        fma2(acc2[a][k], wcd.y, vp[k][3]);
                    }
                }
            }
        }
        #pragma unroll
        for (int a=0;a<7;a++)
            #pragma unroll
            for (int k=0;k<3;k++)
                s_Q[a*QST + r*WS + dj0 + k] = sum2(acc2[a][k]);
    }
    __syncthreads();

    // ---- prefetch b2 region into registers (hidden behind stage2+sort)
    const float* b2t = g_b2 + (size_t)t*CI*HW;
    float vb[CI], vb2[CI];
    {
        int go0 = s_goff[tid];
        int go1 = s_goff[tid+256];
        #pragma unroll
        for (int ci=0;ci<CI;ci++){
            vb[ci]  = b2t[ci*HW+go0];
            vb2[ci] = b2t[ci*HW+go1];
        }
    }

    // ---- stage 2: keys straight into registers
    ull k0, k1;
    {
        int di = tid/WS, dj = tid - WS*di;      // tid < 441 always
        float sc = 0.f;
        #pragma unroll
        for (int a=0;a<7;a++) sc += s_Q[a*QST + s_ro[di*7+a]*WS + dj];
        k0 = ((ull)ordf(sc) << 32) | (unsigned)tid;
        int c1 = tid + 256;
        k1 = 0ull;
        if (c1 < NC){
            int di1 = c1/WS, dj1 = c1 - WS*di1;
            float sc1 = 0.f;
            #pragma unroll
            for (int a=0;a<7;a++) sc1 += s_Q[a*QST + s_ro[di1*7+a]*WS + dj1];
            k1 = ((ull)ordf(sc1) << 32) | (unsigned)c1;
        }
    }
    __syncthreads();   // Q reads done; s_bufB (aliasing Q) may now be written

    // ---- bitonic sort 512 descending: regs + shfl, 9 smem steps
    {
        int p1 = tid + 256;
        #pragma unroll
        for (int k=2; k<=32; k<<=1)
            #pragma unroll
            for (int j=k>>1; j; j>>=1){
                k0 = cmpshfl(k0, tid, j, k);
                k1 = cmpshfl(k1, p1,  j, k);
            }
        int tog = 0;
        #pragma unroll
        for (int k=64; k<=512; k<<=1){
            if (k == 512){ if (k0 < k1){ ull tt=k0; k0=k1; k1=tt; } }
            int jstart = (k>>1) > 128 ? 128 : (k>>1);
            for (int j=jstart; j>=32; j>>=1){
                ull* buf = tog ? s_bufB : s_srt;
                buf[tid] = k0; buf[p1] = k1;
                __syncthreads();
                int pt = tid ^ j;
                ull o0 = buf[pt], o1 = buf[pt+256];
                bool km0 = (((tid & j)==0) == (((tid) & k)==0));
                bool km1 = (((tid & j)==0) == (((p1 ) & k)==0));
                k0 = km0 ? (k0>o0?k0:o0) : (k0<o0?k0:o0);
                k1 = km1 ? (k1>o1?k1:o1) : (k1<o1?k1:o1);
                tog ^= 1;
            }
            #pragma unroll
            for (int j=16; j; j>>=1){
                k0 = cmpshfl(k0, tid, j, k);
                k1 = cmpshfl(k1, p1,  j, k);
            }
        }
    }
    // rank = position; thread tid holds rank tid (descending)
    if (tid < KSEL) s_srt[tid] = k0;
    __syncthreads();

    // ---- softmax over top-100
    {
        float maxs = iordf((unsigned)(s_srt[0] >> 32));
        if (tid < KSEL){
            ull key = s_srt[tid];
            float sc = iordf((unsigned)(key >> 32));
            s_w[tid]   = expf((sc - maxs)*SCALE);
            s_cid[tid] = (int)(key & 0x1FFu);
        }
        __syncthreads();
        if (tid < 32){
            float s = 0.f;
            for (int k=tid; k<KSEL; k+=32) s += s_w[k];
            #pragma unroll
            for (int o=16;o;o>>=1) s += __shfl_xor_sync(0xffffffffu, s, o);
            if (tid == 0) s_w[KSEL] = 1.f/s;
        }
        __syncthreads();
        if (tid < KSEL) s_w[tid] *= s_w[KSEL];
    }

    // ---- commit b2 ci-interleaved (float4) + third chunk + [k][49] offset table
    #pragma unroll
    for (int g=0; g<4; g++){
        s_rg4[g*RGN2 + tid]       = make_float4(vb [4*g],vb [4*g+1],vb [4*g+2],vb [4*g+3]);
        s_rg4[g*RGN2 + tid + 256] = make_float4(vb2[4*g],vb2[4*g+1],vb2[4*g+2],vb2[4*g+3]);
    }
    if (tid + 512 < RGN2){
        int go2 = s_goff[tid+512];
        float v3[CI];
        #pragma unroll
        for (int ci=0;ci<CI;ci++) v3[ci] = b2t[ci*HW+go2];
        #pragma unroll
        for (int g=0; g<4; g++)
            s_rg4[g*RGN2 + tid + 512] = make_float4(v3[4*g],v3[4*g+1],v3[4*g+2],v3[4*g+3]);
    }
    for (int i=tid; i<KSEL*49; i+=NT){
        int k = i/49, p = i - 49*k;
        int c = s_cid[k];
        int pa = p/7, pb = p - 7*pa;
        s_off[k*49 + p] = s_ro[(c/WS)*7 + pa]*RGN + s_co[(c%WS)*7 + pb];
    }
    __syncthreads();

    // ---- aggregation: 196 threads, per-k: 1 LDS.32 off + 1 LDS.32 w + 1 LDS.128 gather
    if (tid < 196){
        int p   = tid % 49;
        int cig = tid / 49;
        const float4* rg = s_rg4 + cig*RGN2;
        float a0=0.f, a1=0.f, a2=0.f, a3=0.f;
        #pragma unroll 4
        for (int k=0; k<KSEL; k++){
            float w   = s_w[k];
            int   off = s_off[k*49 + p];
            float4 v  = rg[off];
            a0 += w*v.x; a1 += w*v.y; a2 += w*v.z; a3 += w*v.w;
        }
        int pa = p/7, pb = p - 7*pa;
        int pix = min(qi+pa,95)*WW + min(qj+pb,95);
        float* accb = g_acc + (size_t)(t*CI + cig*4)*HW + pix;
        atomicAdd(accb,        a0);
        atomicAdd(accb +   HW, a1);
        atomicAdd(accb + 2*HW, a2);
        atomicAdd(accb + 3*HW, a3);
    }
}

// ---------------------------------------------------------------- y = acc/Z ; out = vid + conv1x1(y)
__global__ void k_final(const float* __restrict__ vid, const float* __restrict__ Ww,
                        const float* __restrict__ Wb, float* __restrict__ out){
    __shared__ float sw[C_*CI + C_];
    for (int i=threadIdx.x; i<C_*CI; i+=NT) sw[i] = Ww[i];
    if (threadIdx.x < C_) sw[C_*CI+threadIdx.x] = Wb[threadIdx.x];
    __syncthreads();

    int gid = blockIdx.x*NT + threadIdx.x;
    int t = gid / HW, pix = gid % HW;

    float inv = 1.f / g_Z[pix];
    float y[CI];
    #pragma unroll
    for (int ci=0;ci<CI;ci++) y[ci] = g_acc[(t*CI+ci)*HW + pix]*inv;

    const float* vp = vid + (size_t)t*C_*HW + pix;
    float*       op = out + (size_t)t*C_*HW + pix;
    for (int co=0;co<C_;co++){
        float s = sw[C_*CI+co];
        #pragma unroll
        for (int ci=0;ci<CI;ci++) s += sw[co*CI+ci]*y[ci];
        op[co*HW] = vp[co*HW] + s;
    }
}

// ---------------------------------------------------------------- launch
extern "C" void kernel_launch(void* const* d_in, const int* in_sizes, int n_in,
                              void* d_out, int out_size){
    const float* vid  = (const float*)d_in[0];
    const float* g_w  = (const float*)d_in[1];
    const float* g_b  = (const float*)d_in[2];
    const float* th_w = (const float*)d_in[3];
    const float* th_b = (const float*)d_in[4];
    const float* ph_w = (const float*)d_in[5];
    const float* ph_b = (const float*)d_in[6];
    const float* W_w  = (const float*)d_in[7];
    const float* W_b  = (const float*)d_in[8];
    float* out = (float*)d_out;

    const int SMEM = SM_TOT * 4;   // 75132 B
    cudaFuncSetAttribute(k_score, cudaFuncAttributeMaxDynamicSharedMemorySize, SMEM);

    k_zero  <<<(T_*CI*HW + NT-1)/NT, NT>>>();
    k_proj  <<<T_*HW/NT, NT>>>(vid, g_w, g_b, th_w, th_b, ph_w, ph_b);
    k_zcount<<<NQ, PS*PS>>>();
    k_score <<<T_*NQ, NT, SMEM>>>();
    k_final <<<T_*HW/NT, NT>>>(vid, W_w, W_b, out);
}

// round 9
// speedup vs baseline: 1.3407x; 1.0718x over previous
#include <cuda_runtime.h>
#include <cuda_fp16.h>
#include <math.h>
#include <float.h>

#define T_    4
#define C_    64
#define WW    96
#define HW    9216
#define CI    16
#define PS    7
#define WS    21
#define NQX   24
#define NQ    576
#define NC    441
#define KSEL  100
#define SCALE 10.0f
#define RGN   27
#define RGN2  729
#define NT    256
#define B1P   56
#define QST   (RGN*WS)      // 567

// smem layout (float offsets)
#define SM_B1   0            // 896
#define SM_RG   896          // 11664 (b3 planar; later aliased by fp16 b2)
#define SM_Q    12560        // 3970  (sort buffer B alias + off table)
#define SM_SRT  16530        // u64[512] = 1024 floats (sort buffer A)
#define SM_W    17556        // 104
#define SM_CID  17660        // 100
#define SM_RO   17760        // 147
#define SM_CO   17907        // 147
#define SM_GOFF 18054        // 729
#define SM_TOT  18783        // 75132 bytes

typedef unsigned long long ull;

// scratch (planar layouts)
__device__ float g_b1[T_*CI*HW];
__device__ float g_b2[T_*CI*HW];
__device__ float g_b3[T_*CI*HW];
__device__ float g_acc[T_*CI*HW];

__device__ __forceinline__ int clipi(int v){ return min(max(v,0),95); }
__device__ __forceinline__ unsigned ordf(float f){
    unsigned b = __float_as_uint(f);
    return (b & 0x80000000u) ? ~b : (b | 0x80000000u);
}
__device__ __forceinline__ float iordf(unsigned u){
    unsigned b = (u & 0x80000000u) ? (u & 0x7FFFFFFFu) : ~u;
    return __uint_as_float(b);
}
__device__ __forceinline__ ull pack2(float lo, float hi){
    ull r; asm("mov.b64 %0, {%1, %2};" : "=l"(r) : "f"(lo), "f"(hi)); return r;
}
__device__ __forceinline__ void fma2(ull &acc, ull a, ull b){
    asm("fma.rn.f32x2 %0, %1, %2, %0;" : "+l"(acc) : "l"(a), "l"(b));
}
__device__ __forceinline__ float sum2(ull v){
    return __uint_as_float((unsigned)v) + __uint_as_float((unsigned)(v>>32));
}
__device__ __forceinline__ ull cmpshfl(ull v, int p, int j, int k){
    ull o = __shfl_xor_sync(0xffffffffu, v, j);
    bool keepMax = (((p & j)==0) == ((p & k)==0));
    ull mx = v > o ? v : o, mn = v > o ? o : v;
    return keepMax ? mx : mn;
}
// half2 <-> uint bit casts (register moves)
__device__ __forceinline__ unsigned h2u(__half2 h){
    return *reinterpret_cast<unsigned*>(&h);
}
__device__ __forceinline__ __half2 u2h(unsigned u){
    return *reinterpret_cast<__half2*>(&u);
}

// ---------------------------------------------------------------- fused 3x conv1x1 (+ g_acc zeroing)
__global__ void k_proj(const float* __restrict__ vid,
                       const float* __restrict__ gw, const float* __restrict__ gb,
                       const float* __restrict__ tw, const float* __restrict__ tb,
                       const float* __restrict__ pw, const float* __restrict__ pb){
    __shared__ float sw[3*CI*C_ + 3*CI];
    for (int i=threadIdx.x; i<CI*C_; i+=NT){
        sw[i]          = gw[i];
        sw[CI*C_+i]    = tw[i];
        sw[2*CI*C_+i]  = pw[i];
    }
    if (threadIdx.x < CI){
        sw[3*CI*C_         + threadIdx.x] = gb[threadIdx.x];
        sw[3*CI*C_ +   CI  + threadIdx.x] = tb[threadIdx.x];
        sw[3*CI*C_ + 2*CI  + threadIdx.x] = pb[threadIdx.x];
    }

    int gid = blockIdx.x*NT + threadIdx.x;   // [0, T*HW) = 36864 threads

    // zero g_acc: 589824 floats = 147456 float4, 4 per thread
    {
        float4 z4 = make_float4(0.f,0.f,0.f,0.f);
        float4* az = (float4*)g_acc + (size_t)gid*4;
        az[0]=z4; az[1]=z4; az[2]=z4; az[3]=z4;
    }
    __syncthreads();

    int t = gid / HW, pix = gid % HW;

    float a1[CI], a2[CI], a3[CI];
    #pragma unroll
    for (int o=0;o<CI;o++){
        a1[o] = sw[3*CI*C_ + o];
        a2[o] = sw[3*CI*C_ + CI + o];
        a3[o] = sw[3*CI*C_ + 2*CI + o];
    }
    const float* vp = vid + (size_t)t*C_*HW + pix;
    for (int c=0;c<C_;c++){
        float v = vp[c*HW];
        #pragma unroll
        for (int o=0;o<CI;o++){
            a1[o] += v*sw[o*C_+c];
            a2[o] += v*sw[CI*C_ + o*C_+c];
            a3[o] += v*sw[2*CI*C_ + o*C_+c];
        }
    }
    float* o1 = g_b1 + (size_t)t*CI*HW + pix;
    float* o2 = g_b2 + (size_t)t*CI*HW + pix;
    float* o3 = g_b3 + (size_t)t*CI*HW + pix;
    #pragma unroll
    for (int o=0;o<CI;o++){ o1[o*HW]=a1[o]; o2[o*HW]=a2[o]; o3[o*HW]=a3[o]; }
}

// ---------------------------------------------------------------- main kernel
__global__ void __launch_bounds__(NT, 3) k_score(){
    extern __shared__ float sm[];
    float* s_b1 = sm + SM_B1;
    float* s_rg = sm + SM_RG;
    uint2* s_rgH = (uint2*)(sm + SM_RG);      // fp16 b2, 4 ci per uint2 (aliases s_rg: 5832 <= 11664)
    float* s_Q  = sm + SM_Q;
    ull*   s_srt = (ull*)(sm + SM_SRT);       // sort buffer A + final top-100
    ull*   s_bufB = (ull*)(sm + SM_Q);        // sort buffer B (Q dead during sort)
    float* s_w   = sm + SM_W;
    int*   s_cid = (int*)(sm + SM_CID);
    int*   s_ro  = (int*)(sm + SM_RO);
    int*   s_co  = (int*)(sm + SM_CO);
    int*   s_goff= (int*)(sm + SM_GOFF);
    int*   s_off = (int*)s_Q;                 // [k][49] table, built after sort (4900 <= 3970+1024)

    int blk = blockIdx.x;
    int t = blk / NQ, q = blk % NQ;
    int qi = (q / NQX)*4, qj = (q % NQX)*4;
    int tid = threadIdx.x;

    int rmin = max(qi-10, 0), cmin = max(qj-10, 0);
    bool colAffine = (qj >= 12 && qj <= 76);

    // ---- tables
    if (tid < 147){
        int d_ = tid/7, e_ = tid%7;
        s_ro[tid] = min(clipi(qi + d_ - 10) + e_, 95) - rmin;
        s_co[tid] = min(clipi(qj + d_ - 10) + e_, 95) - cmin;
    }
    for (int i=tid; i<RGN2; i+=NT){
        int rr = i/RGN, cc = i - rr*RGN;
        s_goff[i] = min(rmin+rr,95)*WW + min(cmin+cc,95);
    }
    const float* b1t = g_b1 + (size_t)t*CI*HW;
    for (int i=tid; i<CI*49; i+=NT){
        int ci = i/49, rem = i - 49*ci, a = rem/7, b = rem - 7*a;
        s_b1[ci*B1P + a*8 + b] = b1t[ci*HW + min(qi+a,95)*WW + min(qj+b,95)];
    }
    if (tid < CI*7){
        int ci = tid/7, a = tid - 7*ci;
        s_b1[ci*B1P + a*8 + 7] = 0.f;
    }
    __syncthreads();

    // ---- load b3 region (planar): 1 goff LDS feeds 16 coalesced LDG
    {
        const float* b3t = g_b3 + (size_t)t*CI*HW;
        for (int i=tid; i<RGN2; i+=NT){
            int go = s_goff[i];
            #pragma unroll
            for (int ci=0;ci<CI;ci++) s_rg[ci*RGN2+i] = b3t[ci*HW+go];
        }
    }
    __syncthreads();

    // ---- stage 1: Q[a][r][dj] via f32x2, weights via LDS.128
    if (tid < 189){
        int r = tid/7, dj0 = (tid%7)*3;
        ull acc2[7][3];
        #pragma unroll
        for (int a=0;a<7;a++){ acc2[a][0]=0ull; acc2[a][1]=0ull; acc2[a][2]=0ull; }

        if (colAffine){
            for (int ci=0; ci<CI; ci++){
                const float* row = s_rg + ci*RGN2 + r*RGN + dj0;
                float win[9];
                #pragma unroll
                for (int j=0;j<9;j++) win[j] = row[j];
                ull wp[9];
                #pragma unroll
                for (int b=0;b<8;b++) wp[b] = pack2(win[b], win[b+1]);
                wp[8] = pack2(win[8], 0.f);
                const ulonglong2* wq2 = (const ulonglong2*)(s_b1 + ci*B1P);
                #pragma unroll
                for (int a=0;a<7;a++){
                    ulonglong2 wab = wq2[a*2], wcd = wq2[a*2+1];
                    #pragma unroll
                    for (int k=0;k<3;k++){
                        fma2(acc2[a][k], wab.x, wp[k]);
                        fma2(acc2[a][k], wab.y, wp[k+2]);
                        fma2(acc2[a][k], wcd.x, wp[k+4]);
                        fma2(acc2[a][k], wcd.y, wp[k+6]);
                    }
                }
            }
        } else {
            int clim = 95 - cmin;
            int cb[3];
            #pragma unroll
            for (int k=0;k<3;k++) cb[k] = s_co[(dj0+k)*7];
            for (int ci=0; ci<CI; ci++){
                const float* row = s_rg + ci*RGN2 + r*RGN;
                ull vp[3][4];
                #pragma unroll
                for (int k=0;k<3;k++){
                    float w0=row[min(cb[k]+0,clim)], w1=row[min(cb[k]+1,clim)];
                    float w2=row[min(cb[k]+2,clim)], w3=row[min(cb[k]+3,clim)];
                    float w4=row[min(cb[k]+4,clim)], w5=row[min(cb[k]+5,clim)];
                    float w6=row[min(cb[k]+6,clim)], w7=row[min(cb[k]+7,clim)];
                    vp[k][0]=pack2(w0,w1); vp[k][1]=pack2(w2,w3);
                    vp[k][2]=pack2(w4,w5); vp[k][3]=pack2(w6,w7);
                }
                const ulonglong2* wq2 = (const ulonglong2*)(s_b1 + ci*B1P);
                #pragma unroll
                for (int a=0;a<7;a++){
                    ulonglong2 wab = wq2[a*2], wcd = wq2[a*2+1];
                    #pragma unroll
                    for (int k=0;k<3;k++){
                        fma2(acc2[a][k], wab.x, vp[k][0]);
                        fma2(acc2[a][k], wab.y, vp[k][1]);
                        fma2(acc2[a][k], wcd.x, vp[k][2]);
                        fma2(acc2[a][k], wcd.y, vp[k][3]);
                    }
                }
            }
        }
        #pragma unroll
        for (int a=0;a<7;a++)
            #pragma unroll
            for (int k=0;k<3;k++)
                s_Q[a*QST + r*WS + dj0 + k] = sum2(acc2[a][k]);
    }
    __syncthreads();

    // ---- prefetch b2 region into registers (hidden behind stage2+sort)
    const float* b2t = g_b2 + (size_t)t*CI*HW;
    float vb[CI], vb2[CI];
    {
        int go0 = s_goff[tid];
        int go1 = s_goff[tid+256];
        #pragma unroll
        for (int ci=0;ci<CI;ci++){
            vb[ci]  = b2t[ci*HW+go0];
            vb2[ci] = b2t[ci*HW+go1];
        }
    }

    // ---- stage 2: keys straight into registers
    ull k0, k1;
    {
        int di = tid/WS, dj = tid - WS*di;
        float sc = 0.f;
        #pragma unroll
        for (int a=0;a<7;a++) sc += s_Q[a*QST + s_ro[di*7+a]*WS + dj];
        k0 = ((ull)ordf(sc) << 32) | (unsigned)tid;
        int c1 = tid + 256;
        k1 = 0ull;
        if (c1 < NC){
            int di1 = c1/WS, dj1 = c1 - WS*di1;
            float sc1 = 0.f;
            #pragma unroll
            for (int a=0;a<7;a++) sc1 += s_Q[a*QST + s_ro[di1*7+a]*WS + dj1];
            k1 = ((ull)ordf(sc1) << 32) | (unsigned)c1;
        }
    }
    __syncthreads();   // Q reads done; s_bufB (aliasing Q) may now be written

    // ---- bitonic sort 512 descending: regs + shfl, 9 smem steps
    {
        int p1 = tid + 256;
        #pragma unroll
        for (int k=2; k<=32; k<<=1)
            #pragma unroll
            for (int j=k>>1; j; j>>=1){
                k0 = cmpshfl(k0, tid, j, k);
                k1 = cmpshfl(k1, p1,  j, k);
            }
        int tog = 0;
        #pragma unroll
        for (int k=64; k<=512; k<<=1){
            if (k == 512){ if (k0 < k1){ ull tt=k0; k0=k1; k1=tt; } }
            int jstart = (k>>1) > 128 ? 128 : (k>>1);
            for (int j=jstart; j>=32; j>>=1){
                ull* buf = tog ? s_bufB : s_srt;
                buf[tid] = k0; buf[p1] = k1;
                __syncthreads();
                int pt = tid ^ j;
                ull o0 = buf[pt], o1 = buf[pt+256];
                bool km0 = (((tid & j)==0) == (((tid) & k)==0));
                bool km1 = (((tid & j)==0) == (((p1 ) & k)==0));
                k0 = km0 ? (k0>o0?k0:o0) : (k0<o0?k0:o0);
                k1 = km1 ? (k1>o1?k1:o1) : (k1<o1?k1:o1);
                tog ^= 1;
            }
            #pragma unroll
            for (int j=16; j; j>>=1){
                k0 = cmpshfl(k0, tid, j, k);
                k1 = cmpshfl(k1, p1,  j, k);
            }
        }
    }
    if (tid < KSEL) s_srt[tid] = k0;
    __syncthreads();

    // ---- softmax over top-100
    {
        float maxs = iordf((unsigned)(s_srt[0] >> 32));
        if (tid < KSEL){
            ull key = s_srt[tid];
            float sc = iordf((unsigned)(key >> 32));
            s_w[tid]   = expf((sc - maxs)*SCALE);
            s_cid[tid] = (int)(key & 0x1FFu);
        }
        __syncthreads();
        if (tid < 32){
            float s = 0.f;
            for (int k=tid; k<KSEL; k+=32) s += s_w[k];
            #pragma unroll
            for (int o=16;o;o>>=1) s += __shfl_xor_sync(0xffffffffu, s, o);
            if (tid == 0) s_w[KSEL] = 1.f/s;
        }
        __syncthreads();
        if (tid < KSEL) s_w[tid] *= s_w[KSEL];
    }

    // ---- commit b2 as fp16 ci-interleaved (uint2 = 4 ci) + third chunk + [k][49] offsets
    #pragma unroll
    for (int g=0; g<4; g++){
        uint2 u0, u1;
        u0.x = h2u(__floats2half2_rn(vb [4*g],  vb [4*g+1]));
        u0.y = h2u(__floats2half2_rn(vb [4*g+2],vb [4*g+3]));
        u1.x = h2u(__floats2half2_rn(vb2[4*g],  vb2[4*g+1]));
        u1.y = h2u(__floats2half2_rn(vb2[4*g+2],vb2[4*g+3]));
        s_rgH[g*RGN2 + tid]       = u0;
        s_rgH[g*RGN2 + tid + 256] = u1;
    }
    if (tid + 512 < RGN2){
        int go2 = s_goff[tid+512];
        float v3[CI];
        #pragma unroll
        for (int ci=0;ci<CI;ci++) v3[ci] = b2t[ci*HW+go2];
        #pragma unroll
        for (int g=0; g<4; g++){
            uint2 u2;
            u2.x = h2u(__floats2half2_rn(v3[4*g],  v3[4*g+1]));
            u2.y = h2u(__floats2half2_rn(v3[4*g+2],v3[4*g+3]));
            s_rgH[g*RGN2 + tid + 512] = u2;
        }
    }
    for (int i=tid; i<KSEL*49; i+=NT){
        int k = i/49, p = i - 49*k;
        int c = s_cid[k];
        int pa = p/7, pb = p - 7*pa;
        s_off[k*49 + p] = s_ro[(c/WS)*7 + pa]*RGN + s_co[(c%WS)*7 + pb];
    }
    __syncthreads();

    // ---- aggregation: 196 threads, per-k: LDS.32 off + LDS.64 fp16 gather; w via float4
    if (tid < 196){
        int p   = tid % 49;
        int cig = tid / 49;
        const uint2* rg = s_rgH + cig*RGN2;
        float a0=0.f, a1=0.f, a2=0.f, a3=0.f;
        #pragma unroll 2
        for (int k=0; k<KSEL; k+=4){
            float4 w4 = *(const float4*)(s_w + k);
            #pragma unroll
            for (int u=0; u<4; u++){
                float w = (u==0)?w4.x:(u==1)?w4.y:(u==2)?w4.z:w4.w;
                int off = s_off[(k+u)*49 + p];
                uint2 v = rg[off];
                float2 f0 = __half22float2(u2h(v.x));
                float2 f1 = __half22float2(u2h(v.y));
                a0 += w*f0.x; a1 += w*f0.y; a2 += w*f1.x; a3 += w*f1.y;
            }
        }
        int pa = p/7, pb = p - 7*pa;
        int pix = min(qi+pa,95)*WW + min(qj+pb,95);
        float* accb = g_acc + (size_t)(t*CI + cig*4)*HW + pix;
        atomicAdd(accb,        a0);
        atomicAdd(accb +   HW, a1);
        atomicAdd(accb + 2*HW, a2);
        atomicAdd(accb + 3*HW, a3);
    }
}

// ---------------------------------------------------------------- y = acc/Z(analytic) ; out = vid + conv1x1(y)
__global__ void k_final(const float* __restrict__ vid, const float* __restrict__ Ww,
                        const float* __restrict__ Wb, float* __restrict__ out){
    __shared__ float sw[C_*CI + C_];
    for (int i=threadIdx.x; i<C_*CI; i+=NT) sw[i] = Ww[i];
    if (threadIdx.x < C_) sw[C_*CI+threadIdx.x] = Wb[threadIdx.x];
    __syncthreads();

    int gid = blockIdx.x*NT + threadIdx.x;
    int t = gid / HW, pix = gid % HW;
    int row = pix / WW, col = pix - row*WW;

    // analytic overlap count: Z = cr(row)*cc(col)
    int cr = 0, cc = 0;
    #pragma unroll
    for (int a=0;a<7;a++){
        int v = row - a; cr += (v >= 0 && v <= 92 && (v & 3) == 0);
        int u = col - a; cc += (u >= 0 && u <= 92 && (u & 3) == 0);
    }
    if (row == 95) cr += 3;
    if (col == 95) cc += 3;
    float inv = 1.f / (float)(cr*cc);

    float y[CI];
    #pragma unroll
    for (int ci=0;ci<CI;ci++) y[ci] = g_acc[(t*CI+ci)*HW + pix]*inv;

    const float* vp = vid + (size_t)t*C_*HW + pix;
    float*       op = out + (size_t)t*C_*HW + pix;
    for (int co=0;co<C_;co++){
        float s = sw[C_*CI+co];
        #pragma unroll
        for (int ci=0;ci<CI;ci++) s += sw[co*CI+ci]*y[ci];
        op[co*HW] = vp[co*HW] + s;
    }
}

// ---------------------------------------------------------------- launch
extern "C" void kernel_launch(void* const* d_in, const int* in_sizes, int n_in,
                              void* d_out, int out_size){
    const float* vid  = (const float*)d_in[0];
    const float* g_w  = (const float*)d_in[1];
    const float* g_b  = (const float*)d_in[2];
    const float* th_w = (const float*)d_in[3];
    const float* th_b = (const float*)d_in[4];
    const float* ph_w = (const float*)d_in[5];
    const float* ph_b = (const float*)d_in[6];
    const float* W_w  = (const float*)d_in[7];
    const float* W_b  = (const float*)d_in[8];
    float* out = (float*)d_out;

    const int SMEM = SM_TOT * 4;   // 75132 B
    cudaFuncSetAttribute(k_score, cudaFuncAttributeMaxDynamicSharedMemorySize, SMEM);

    k_proj  <<<T_*HW/NT, NT>>>(vid, g_w, g_b, th_w, th_b, ph_w, ph_b);
    k_score <<<T_*NQ, NT, SMEM>>>();
    k_final <<<T_*HW/NT, NT>>>(vid, W_w, W_b, out);
}

// round 10
// speedup vs baseline: 1.4531x; 1.0838x over previous
#include <cuda_runtime.h>
#include <cuda_fp16.h>
#include <math.h>
#include <float.h>

#define T_    4
#define C_    64
#define WW    96
#define HW    9216
#define CI    16
#define PS    7
#define WS    21
#define NQX   24
#define NQ    576
#define NC    441
#define KSEL  100
#define SCALE 10.0f
#define RGN   27
#define RGN2  729
#define NT    256
#define B1P   56
#define QST   (RGN*WS)      // 567

// smem layout (float offsets)
#define SM_B1   0            // 896
#define SM_RG   896          // 11664 (b3 planar; later aliased by fp16 b2)
#define SM_Q    12560        // 3970  (sort buffer B alias + off table)
#define SM_SRT  16530        // u64[512] = 1024 floats (sort buffer A)
#define SM_W    17556        // 104
#define SM_CID  17660        // 100
#define SM_RO   17760        // 147
#define SM_CO   17907        // 147
#define SM_GOFF 18054        // 729
#define SM_TOT  18783        // 75132 bytes

typedef unsigned long long ull;

// scratch (planar layouts)
__device__ float g_b1[T_*CI*HW];
__device__ float g_b2[T_*CI*HW];
__device__ float g_b3[T_*CI*HW];
__device__ float g_acc[T_*CI*HW];

__device__ __forceinline__ int clipi(int v){ return min(max(v,0),95); }
__device__ __forceinline__ unsigned ordf(float f){
    unsigned b = __float_as_uint(f);
    return (b & 0x80000000u) ? ~b : (b | 0x80000000u);
}
__device__ __forceinline__ float iordf(unsigned u){
    unsigned b = (u & 0x80000000u) ? (u & 0x7FFFFFFFu) : ~u;
    return __uint_as_float(b);
}
__device__ __forceinline__ ull pack2(float lo, float hi){
    ull r; asm("mov.b64 %0, {%1, %2};" : "=l"(r) : "f"(lo), "f"(hi)); return r;
}
__device__ __forceinline__ void fma2(ull &acc, ull a, ull b){
    asm("fma.rn.f32x2 %0, %1, %2, %0;" : "+l"(acc) : "l"(a), "l"(b));
}
__device__ __forceinline__ float sum2(ull v){
    return __uint_as_float((unsigned)v) + __uint_as_float((unsigned)(v>>32));
}
__device__ __forceinline__ ull cmpshfl(ull v, int p, int j, int k){
    ull o = __shfl_xor_sync(0xffffffffu, v, j);
    bool keepMax = (((p & j)==0) == ((p & k)==0));
    ull mx = v > o ? v : o, mn = v > o ? o : v;
    return keepMax ? mx : mn;
}
__device__ __forceinline__ unsigned h2u(__half2 h){
    return *reinterpret_cast<unsigned*>(&h);
}
__device__ __forceinline__ __half2 u2h(unsigned u){
    return *reinterpret_cast<__half2*>(&u);
}

// ---------------------------------------------------------------- fused 3x conv1x1 (4-way split) + g_acc zero
// grid = 4*144 blocks: sub = blockIdx.x / 144 selects output-channel quarter
__global__ void __launch_bounds__(NT) k_proj(const float* __restrict__ vid,
                       const float* __restrict__ gw, const float* __restrict__ gb,
                       const float* __restrict__ tw, const float* __restrict__ tb,
                       const float* __restrict__ pw, const float* __restrict__ pb){
    __shared__ __align__(16) float sw[3*CI*C_ + 3*CI];
    for (int i=threadIdx.x; i<CI*C_; i+=NT){
        sw[i]          = gw[i];
        sw[CI*C_+i]    = tw[i];
        sw[2*CI*C_+i]  = pw[i];
    }
    if (threadIdx.x < CI){
        sw[3*CI*C_         + threadIdx.x] = gb[threadIdx.x];
        sw[3*CI*C_ +   CI  + threadIdx.x] = tb[threadIdx.x];
        sw[3*CI*C_ + 2*CI  + threadIdx.x] = pb[threadIdx.x];
    }

    int gid = blockIdx.x*NT + threadIdx.x;      // [0, 4*T*HW)
    // zero g_acc: 589824 floats = 147456 float4, one per thread
    ((float4*)g_acc)[gid] = make_float4(0.f,0.f,0.f,0.f);
    __syncthreads();

    int sub = blockIdx.x / 144;                 // 0..3 -> output channels [4*sub, 4*sub+4)
    int pid = (blockIdx.x % 144)*NT + threadIdx.x;   // [0, T*HW)
    int t = pid / HW, pix = pid % HW;
    int o0 = sub*4;

    float a1[4], a2[4], a3[4];
    #pragma unroll
    for (int u=0;u<4;u++){
        a1[u] = sw[3*CI*C_ + o0+u];
        a2[u] = sw[3*CI*C_ + CI + o0+u];
        a3[u] = sw[3*CI*C_ + 2*CI + o0+u];
    }
    const float* vp = vid + (size_t)t*C_*HW + pix;
    #pragma unroll 4
    for (int c=0;c<C_;c+=4){
        float v0 = vp[c*HW], v1 = vp[(c+1)*HW], v2 = vp[(c+2)*HW], v3 = vp[(c+3)*HW];
        #pragma unroll
        for (int u=0;u<4;u++){
            int o = o0+u;
            float4 w1 = *(const float4*)(sw + o*C_ + c);
            float4 w2 = *(const float4*)(sw + CI*C_ + o*C_ + c);
            float4 w3 = *(const float4*)(sw + 2*CI*C_ + o*C_ + c);
            a1[u] += v0*w1.x + v1*w1.y + v2*w1.z + v3*w1.w;
            a2[u] += v0*w2.x + v1*w2.y + v2*w2.z + v3*w2.w;
            a3[u] += v0*w3.x + v1*w3.y + v2*w3.z + v3*w3.w;
        }
    }
    float* b = (float*)0;
    float* o1 = g_b1 + (size_t)t*CI*HW + pix;
    float* o2 = g_b2 + (size_t)t*CI*HW + pix;
    float* o3 = g_b3 + (size_t)t*CI*HW + pix;
    (void)b;
    #pragma unroll
    for (int u=0;u<4;u++){
        o1[(o0+u)*HW] = a1[u];
        o2[(o0+u)*HW] = a2[u];
        o3[(o0+u)*HW] = a3[u];
    }
}

// ---------------------------------------------------------------- main kernel (unchanged from R9)
__global__ void __launch_bounds__(NT, 3) k_score(){
    extern __shared__ float sm[];
    float* s_b1 = sm + SM_B1;
    float* s_rg = sm + SM_RG;
    uint2* s_rgH = (uint2*)(sm + SM_RG);
    float* s_Q  = sm + SM_Q;
    ull*   s_srt = (ull*)(sm + SM_SRT);
    ull*   s_bufB = (ull*)(sm + SM_Q);
    float* s_w   = sm + SM_W;
    int*   s_cid = (int*)(sm + SM_CID);
    int*   s_ro  = (int*)(sm + SM_RO);
    int*   s_co  = (int*)(sm + SM_CO);
    int*   s_goff= (int*)(sm + SM_GOFF);
    int*   s_off = (int*)s_Q;

    int blk = blockIdx.x;
    int t = blk / NQ, q = blk % NQ;
    int qi = (q / NQX)*4, qj = (q % NQX)*4;
    int tid = threadIdx.x;

    int rmin = max(qi-10, 0), cmin = max(qj-10, 0);
    bool colAffine = (qj >= 12 && qj <= 76);

    // ---- tables
    if (tid < 147){
        int d_ = tid/7, e_ = tid%7;
        s_ro[tid] = min(clipi(qi + d_ - 10) + e_, 95) - rmin;
        s_co[tid] = min(clipi(qj + d_ - 10) + e_, 95) - cmin;
    }
    for (int i=tid; i<RGN2; i+=NT){
        int rr = i/RGN, cc = i - rr*RGN;
        s_goff[i] = min(rmin+rr,95)*WW + min(cmin+cc,95);
    }
    const float* b1t = g_b1 + (size_t)t*CI*HW;
    for (int i=tid; i<CI*49; i+=NT){
        int ci = i/49, rem = i - 49*ci, a = rem/7, b = rem - 7*a;
        s_b1[ci*B1P + a*8 + b] = b1t[ci*HW + min(qi+a,95)*WW + min(qj+b,95)];
    }
    if (tid < CI*7){
        int ci = tid/7, a = tid - 7*ci;
        s_b1[ci*B1P + a*8 + 7] = 0.f;
    }
    __syncthreads();

    // ---- load b3 region (planar)
    {
        const float* b3t = g_b3 + (size_t)t*CI*HW;
        for (int i=tid; i<RGN2; i+=NT){
            int go = s_goff[i];
            #pragma unroll
            for (int ci=0;ci<CI;ci++) s_rg[ci*RGN2+i] = b3t[ci*HW+go];
        }
    }
    __syncthreads();

    // ---- stage 1: Q[a][r][dj] via f32x2, weights via LDS.128
    if (tid < 189){
        int r = tid/7, dj0 = (tid%7)*3;
        ull acc2[7][3];
        #pragma unroll
        for (int a=0;a<7;a++){ acc2[a][0]=0ull; acc2[a][1]=0ull; acc2[a][2]=0ull; }

        if (colAffine){
            for (int ci=0; ci<CI; ci++){
                const float* row = s_rg + ci*RGN2 + r*RGN + dj0;
                float win[9];
                #pragma unroll
                for (int j=0;j<9;j++) win[j] = row[j];
                ull wp[9];
                #pragma unroll
                for (int b=0;b<8;b++) wp[b] = pack2(win[b], win[b+1]);
                wp[8] = pack2(win[8], 0.f);
                const ulonglong2* wq2 = (const ulonglong2*)(s_b1 + ci*B1P);
                #pragma unroll
                for (int a=0;a<7;a++){
                    ulonglong2 wab = wq2[a*2], wcd = wq2[a*2+1];
                    #pragma unroll
                    for (int k=0;k<3;k++){
                        fma2(acc2[a][k], wab.x, wp[k]);
                        fma2(acc2[a][k], wab.y, wp[k+2]);
                        fma2(acc2[a][k], wcd.x, wp[k+4]);
                        fma2(acc2[a][k], wcd.y, wp[k+6]);
                    }
                }
            }
        } else {
            int clim = 95 - cmin;
            int cb[3];
            #pragma unroll
            for (int k=0;k<3;k++) cb[k] = s_co[(dj0+k)*7];
            for (int ci=0; ci<CI; ci++){
                const float* row = s_rg + ci*RGN2 + r*RGN;
                ull vp[3][4];
                #pragma unroll
                for (int k=0;k<3;k++){
                    float w0=row[min(cb[k]+0,clim)], w1=row[min(cb[k]+1,clim)];
                    float w2=row[min(cb[k]+2,clim)], w3=row[min(cb[k]+3,clim)];
                    float w4=row[min(cb[k]+4,clim)], w5=row[min(cb[k]+5,clim)];
                    float w6=row[min(cb[k]+6,clim)], w7=row[min(cb[k]+7,clim)];
                    vp[k][0]=pack2(w0,w1); vp[k][1]=pack2(w2,w3);
                    vp[k][2]=pack2(w4,w5); vp[k][3]=pack2(w6,w7);
                }
                const ulonglong2* wq2 = (const ulonglong2*)(s_b1 + ci*B1P);
                #pragma unroll
                for (int a=0;a<7;a++){
                    ulonglong2 wab = wq2[a*2], wcd = wq2[a*2+1];
                    #pragma unroll
                    for (int k=0;k<3;k++){
                        fma2(acc2[a][k], wab.x, vp[k][0]);
                        fma2(acc2[a][k], wab.y, vp[k][1]);
                        fma2(acc2[a][k], wcd.x, vp[k][2]);
                        fma2(acc2[a][k], wcd.y, vp[k][3]);
                    }
                }
            }
        }
        #pragma unroll
        for (int a=0;a<7;a++)
            #pragma unroll
            for (int k=0;k<3;k++)
                s_Q[a*QST + r*WS + dj0 + k] = sum2(acc2[a][k]);
    }
    __syncthreads();

    // ---- prefetch b2 region into registers (hidden behind stage2+sort)
    const float* b2t = g_b2 + (size_t)t*CI*HW;
    float vb[CI], vb2[CI];
    {
        int go0 = s_goff[tid];
        int go1 = s_goff[tid+256];
        #pragma unroll
        for (int ci=0;ci<CI;ci++){
            vb[ci]  = b2t[ci*HW+go0];
            vb2[ci] = b2t[ci*HW+go1];
        }
    }

    // ---- stage 2: keys straight into registers
    ull k0, k1;
    {
        int di = tid/WS, dj = tid - WS*di;
        float sc = 0.f;
        #pragma unroll
        for (int a=0;a<7;a++) sc += s_Q[a*QST + s_ro[di*7+a]*WS + dj];
        k0 = ((ull)ordf(sc) << 32) | (unsigned)tid;
        int c1 = tid + 256;
        k1 = 0ull;
        if (c1 < NC){
            int di1 = c1/WS, dj1 = c1 - WS*di1;
            float sc1 = 0.f;
            #pragma unroll
            for (int a=0;a<7;a++) sc1 += s_Q[a*QST + s_ro[di1*7+a]*WS + dj1];
            k1 = ((ull)ordf(sc1) << 32) | (unsigned)c1;
        }
    }
    __syncthreads();

    // ---- bitonic sort 512 descending: regs + shfl, 9 smem steps
    {
        int p1 = tid + 256;
        #pragma unroll
        for (int k=2; k<=32; k<<=1)
            #pragma unroll
            for (int j=k>>1; j; j>>=1){
                k0 = cmpshfl(k0, tid, j, k);
                k1 = cmpshfl(k1, p1,  j, k);
            }
        int tog = 0;
        #pragma unroll
        for (int k=64; k<=512; k<<=1){
            if (k == 512){ if (k0 < k1){ ull tt=k0; k0=k1; k1=tt; } }
            int jstart = (k>>1) > 128 ? 128 : (k>>1);
            for (int j=jstart; j>=32; j>>=1){
                ull* buf = tog ? s_bufB : s_srt;
                buf[tid] = k0; buf[p1] = k1;
                __syncthreads();
                int pt = tid ^ j;
                ull o0 = buf[pt], o1 = buf[pt+256];
                bool km0 = (((tid & j)==0) == (((tid) & k)==0));
                bool km1 = (((tid & j)==0) == (((p1 ) & k)==0));
                k0 = km0 ? (k0>o0?k0:o0) : (k0<o0?k0:o0);
                k1 = km1 ? (k1>o1?k1:o1) : (k1<o1?k1:o1);
                tog ^= 1;
            }
            #pragma unroll
            for (int j=16; j; j>>=1){
                k0 = cmpshfl(k0, tid, j, k);
                k1 = cmpshfl(k1, p1,  j, k);
            }
        }
    }
    if (tid < KSEL) s_srt[tid] = k0;
    __syncthreads();

    // ---- softmax over top-100
    {
        float maxs = iordf((unsigned)(s_srt[0] >> 32));
        if (tid < KSEL){
            ull key = s_srt[tid];
            float sc = iordf((unsigned)(key >> 32));
            s_w[tid]   = expf((sc - maxs)*SCALE);
            s_cid[tid] = (int)(key & 0x1FFu);
        }
        __syncthreads();
        if (tid < 32){
            float s = 0.f;
            for (int k=tid; k<KSEL; k+=32) s += s_w[k];
            #pragma unroll
            for (int o=16;o;o>>=1) s += __shfl_xor_sync(0xffffffffu, s, o);
            if (tid == 0) s_w[KSEL] = 1.f/s;
        }
        __syncthreads();
        if (tid < KSEL) s_w[tid] *= s_w[KSEL];
    }

    // ---- commit b2 as fp16 ci-interleaved + third chunk + [k][49] offsets
    #pragma unroll
    for (int g=0; g<4; g++){
        uint2 u0, u1;
        u0.x = h2u(__floats2half2_rn(vb [4*g],  vb [4*g+1]));
        u0.y = h2u(__floats2half2_rn(vb [4*g+2],vb [4*g+3]));
        u1.x = h2u(__floats2half2_rn(vb2[4*g],  vb2[4*g+1]));
        u1.y = h2u(__floats2half2_rn(vb2[4*g+2],vb2[4*g+3]));
        s_rgH[g*RGN2 + tid]       = u0;
        s_rgH[g*RGN2 + tid + 256] = u1;
    }
    if (tid + 512 < RGN2){
        int go2 = s_goff[tid+512];
        float v3[CI];
        #pragma unroll
        for (int ci=0;ci<CI;ci++) v3[ci] = b2t[ci*HW+go2];
        #pragma unroll
        for (int g=0; g<4; g++){
            uint2 u2;
            u2.x = h2u(__floats2half2_rn(v3[4*g],  v3[4*g+1]));
            u2.y = h2u(__floats2half2_rn(v3[4*g+2],v3[4*g+3]));
            s_rgH[g*RGN2 + tid + 512] = u2;
        }
    }
    for (int i=tid; i<KSEL*49; i+=NT){
        int k = i/49, p = i - 49*k;
        int c = s_cid[k];
        int pa = p/7, pb = p - 7*pa;
        s_off[k*49 + p] = s_ro[(c/WS)*7 + pa]*RGN + s_co[(c%WS)*7 + pb];
    }
    __syncthreads();

    // ---- aggregation: 196 threads, per-k: LDS.32 off + LDS.64 fp16 gather
    if (tid < 196){
        int p   = tid % 49;
        int cig = tid / 49;
        const uint2* rg = s_rgH + cig*RGN2;
        float a0=0.f, a1=0.f, a2=0.f, a3=0.f;
        #pragma unroll 2
        for (int k=0; k<KSEL; k+=4){
            float4 w4 = *(const float4*)(s_w + k);
            #pragma unroll
            for (int u=0; u<4; u++){
                float w = (u==0)?w4.x:(u==1)?w4.y:(u==2)?w4.z:w4.w;
                int off = s_off[(k+u)*49 + p];
                uint2 v = rg[off];
                float2 f0 = __half22float2(u2h(v.x));
                float2 f1 = __half22float2(u2h(v.y));
                a0 += w*f0.x; a1 += w*f0.y; a2 += w*f1.x; a3 += w*f1.y;
            }
        }
        int pa = p/7, pb = p - 7*pa;
        int pix = min(qi+pa,95)*WW + min(qj+pb,95);
        float* accb = g_acc + (size_t)(t*CI + cig*4)*HW + pix;
        atomicAdd(accb,        a0);
        atomicAdd(accb +   HW, a1);
        atomicAdd(accb + 2*HW, a2);
        atomicAdd(accb + 3*HW, a3);
    }
}

// ---------------------------------------------------------------- final (2-way split over co)
__global__ void __launch_bounds__(NT) k_final(const float* __restrict__ vid, const float* __restrict__ Ww,
                        const float* __restrict__ Wb, float* __restrict__ out){
    __shared__ __align__(16) float sw[C_*CI + C_];
    for (int i=threadIdx.x; i<C_*CI; i+=NT) sw[i] = Ww[i];
    if (threadIdx.x < C_) sw[C_*CI+threadIdx.x] = Wb[threadIdx.x];
    __syncthreads();

    int sub = blockIdx.x / 144;                 // 0..1 -> co range [32*sub, 32*sub+32)
    int pid = (blockIdx.x % 144)*NT + threadIdx.x;
    int t = pid / HW, pix = pid % HW;
    int row = pix / WW, col = pix - row*WW;

    // analytic overlap count: Z = cr(row)*cc(col)
    int cr = 0, cc = 0;
    #pragma unroll
    for (int a=0;a<7;a++){
        int v = row - a; cr += (v >= 0 && v <= 92 && (v & 3) == 0);
        int u = col - a; cc += (u >= 0 && u <= 92 && (u & 3) == 0);
    }
    if (row == 95) cr += 3;
    if (col == 95) cc += 3;
    float inv = 1.f / (float)(cr*cc);

    float y[CI];
    #pragma unroll
    for (int ci=0;ci<CI;ci++) y[ci] = g_acc[(t*CI+ci)*HW + pix]*inv;

    const float* vp = vid + (size_t)t*C_*HW + pix;
    float*       op = out + (size_t)t*C_*HW + pix;
    int co0 = sub*32;
    #pragma unroll 4
    for (int u=0; u<32; u++){
        int co = co0 + u;
        float s = sw[C_*CI+co];
        #pragma unroll
        for (int g=0; g<4; g++){
            float4 w4 = *(const float4*)(sw + co*CI + 4*g);
            s += w4.x*y[4*g] + w4.y*y[4*g+1] + w4.z*y[4*g+2] + w4.w*y[4*g+3];
        }
        op[co*HW] = vp[co*HW] + s;
    }
}

// ---------------------------------------------------------------- launch
extern "C" void kernel_launch(void* const* d_in, const int* in_sizes, int n_in,
                              void* d_out, int out_size){
    const float* vid  = (const float*)d_in[0];
    const float* g_w  = (const float*)d_in[1];
    const float* g_b  = (const float*)d_in[2];
    const float* th_w = (const float*)d_in[3];
    const float* th_b = (const float*)d_in[4];
    const float* ph_w = (const float*)d_in[5];
    const float* ph_b = (const float*)d_in[6];
    const float* W_w  = (const float*)d_in[7];
    const float* W_b  = (const float*)d_in[8];
    float* out = (float*)d_out;

    const int SMEM = SM_TOT * 4;   // 75132 B
    cudaFuncSetAttribute(k_score, cudaFuncAttributeMaxDynamicSharedMemorySize, SMEM);

    k_proj  <<<4*144, NT>>>(vid, g_w, g_b, th_w, th_b, ph_w, ph_b);
    k_score <<<T_*NQ, NT, SMEM>>>();
    k_final <<<2*144, NT>>>(vid, W_w, W_b, out);
}

// round 11
// speedup vs baseline: 1.4735x; 1.0141x over previous
#include <cuda_runtime.h>
#include <cuda_fp16.h>
#include <math.h>
#include <float.h>

#define T_    4
#define C_    64
#define WW    96
#define HW    9216
#define CI    16
#define PS    7
#define WS    21
#define NQX   24
#define NQ    576
#define NC    441
#define KSEL  100
#define SCALE 10.0f
#define RGN   27
#define RGN2  729
#define NT    256
#define B1P   56
#define QST   (RGN*WS)      // 567

// smem layout (float offsets)
#define SM_B1   0            // 896
#define SM_RG   896          // 11664 (b3 planar fp32; later aliased by fp16 b2)
#define SM_Q    12560        // 3970  (sort buffer B alias + off table)
#define SM_SRT  16530        // u64[512] = 1024 floats (sort buffer A)
#define SM_W    17556        // 104
#define SM_CID  17660        // 100
#define SM_RO   17760        // 147
#define SM_CO   17907        // 147
#define SM_GOFF 18054        // 729
#define SM_TOT  18783        // 75132 bytes

typedef unsigned long long ull;

// scratch: pixel-major layouts. b1/b3: [t*HW][16] fp32 ; b2h: [t*HW][16] fp16
__device__ __align__(16) float    g_b1[(size_t)T_*HW*CI];
__device__ __align__(16) float    g_b3[(size_t)T_*HW*CI];
__device__ __align__(16) unsigned g_b2h[(size_t)T_*HW*8];
__device__ __align__(16) float    g_acc[T_*CI*HW];

__device__ __forceinline__ int clipi(int v){ return min(max(v,0),95); }
__device__ __forceinline__ unsigned ordf(float f){
    unsigned b = __float_as_uint(f);
    return (b & 0x80000000u) ? ~b : (b | 0x80000000u);
}
__device__ __forceinline__ float iordf(unsigned u){
    unsigned b = (u & 0x80000000u) ? (u & 0x7FFFFFFFu) : ~u;
    return __uint_as_float(b);
}
__device__ __forceinline__ ull pack2(float lo, float hi){
    ull r; asm("mov.b64 %0, {%1, %2};" : "=l"(r) : "f"(lo), "f"(hi)); return r;
}
__device__ __forceinline__ void fma2(ull &acc, ull a, ull b){
    asm("fma.rn.f32x2 %0, %1, %2, %0;" : "+l"(acc) : "l"(a), "l"(b));
}
__device__ __forceinline__ float sum2(ull v){
    return __uint_as_float((unsigned)v) + __uint_as_float((unsigned)(v>>32));
}
__device__ __forceinline__ ull cmpshfl(ull v, int p, int j, int k){
    ull o = __shfl_xor_sync(0xffffffffu, v, j);
    bool keepMax = (((p & j)==0) == ((p & k)==0));
    ull mx = v > o ? v : o, mn = v > o ? o : v;
    return keepMax ? mx : mn;
}
__device__ __forceinline__ unsigned h2u(__half2 h){
    return *reinterpret_cast<unsigned*>(&h);
}
__device__ __forceinline__ __half2 u2h(unsigned u){
    return *reinterpret_cast<__half2*>(&u);
}

// ---------------------------------------------------------------- fused 3x conv1x1 (4-way split) + g_acc zero
__global__ void __launch_bounds__(NT) k_proj(const float* __restrict__ vid,
                       const float* __restrict__ gw, const float* __restrict__ gb,
                       const float* __restrict__ tw, const float* __restrict__ tb,
                       const float* __restrict__ pw, const float* __restrict__ pb){
    __shared__ __align__(16) float sw[3*CI*C_ + 3*CI];
    for (int i=threadIdx.x; i<CI*C_; i+=NT){
        sw[i]          = gw[i];
        sw[CI*C_+i]    = tw[i];
        sw[2*CI*C_+i]  = pw[i];
    }
    if (threadIdx.x < CI){
        sw[3*CI*C_         + threadIdx.x] = gb[threadIdx.x];
        sw[3*CI*C_ +   CI  + threadIdx.x] = tb[threadIdx.x];
        sw[3*CI*C_ + 2*CI  + threadIdx.x] = pb[threadIdx.x];
    }

    int gid = blockIdx.x*NT + threadIdx.x;      // [0, 4*T*HW)
    ((float4*)g_acc)[gid] = make_float4(0.f,0.f,0.f,0.f);
    __syncthreads();

    int sub = blockIdx.x / 144;                 // output channels [4*sub, 4*sub+4)
    int pid = (blockIdx.x % 144)*NT + threadIdx.x;   // [0, T*HW)
    int t = pid / HW, pix = pid % HW;
    int o0 = sub*4;

    float a1[4], a2[4], a3[4];
    #pragma unroll
    for (int u=0;u<4;u++){
        a1[u] = sw[3*CI*C_ + o0+u];
        a2[u] = sw[3*CI*C_ + CI + o0+u];
        a3[u] = sw[3*CI*C_ + 2*CI + o0+u];
    }
    const float* vp = vid + (size_t)t*C_*HW + pix;
    #pragma unroll 4
    for (int c=0;c<C_;c+=4){
        float v0 = vp[c*HW], v1 = vp[(c+1)*HW], v2 = vp[(c+2)*HW], v3 = vp[(c+3)*HW];
        #pragma unroll
        for (int u=0;u<4;u++){
            int o = o0+u;
            float4 w1 = *(const float4*)(sw + o*C_ + c);
            float4 w2 = *(const float4*)(sw + CI*C_ + o*C_ + c);
            float4 w3 = *(const float4*)(sw + 2*CI*C_ + o*C_ + c);
            a1[u] += v0*w1.x + v1*w1.y + v2*w1.z + v3*w1.w;
            a2[u] += v0*w2.x + v1*w2.y + v2*w2.z + v3*w2.w;
            a3[u] += v0*w3.x + v1*w3.y + v2*w3.z + v3*w3.w;
        }
    }
    // pixel-major writes: b1/b3 float4 slot, b2 fp16 uint2 slot
    ((float4*)g_b1)[(size_t)pid*4 + sub] = make_float4(a1[0],a1[1],a1[2],a1[3]);
    ((float4*)g_b3)[(size_t)pid*4 + sub] = make_float4(a3[0],a3[1],a3[2],a3[3]);
    uint2 u2v;
    u2v.x = h2u(__floats2half2_rn(a2[0], a2[1]));
    u2v.y = h2u(__floats2half2_rn(a2[2], a2[3]));
    ((uint2*)g_b2h)[(size_t)pid*4 + sub] = u2v;
}

// ---------------------------------------------------------------- main kernel
__global__ void __launch_bounds__(NT, 3) k_score(){
    extern __shared__ float sm[];
    float* s_b1 = sm + SM_B1;
    float* s_rg = sm + SM_RG;
    uint2* s_rgH = (uint2*)(sm + SM_RG);      // fp16 b2, 4 ci per uint2 (aliases s_rg)
    float* s_Q  = sm + SM_Q;
    ull*   s_srt = (ull*)(sm + SM_SRT);
    ull*   s_bufB = (ull*)(sm + SM_Q);
    float* s_w   = sm + SM_W;
    int*   s_cid = (int*)(sm + SM_CID);
    int*   s_ro  = (int*)(sm + SM_RO);
    int*   s_co  = (int*)(sm + SM_CO);
    int*   s_goff= (int*)(sm + SM_GOFF);
    int*   s_off = (int*)s_Q;

    int blk = blockIdx.x;
    int t = blk / NQ, q = blk % NQ;
    int qi = (q / NQX)*4, qj = (q % NQX)*4;
    int tid = threadIdx.x;

    int rmin = max(qi-10, 0), cmin = max(qj-10, 0);
    bool colAffine = (qj >= 12 && qj <= 76);

    // ---- tables
    if (tid < 147){
        int d_ = tid/7, e_ = tid%7;
        s_ro[tid] = min(clipi(qi + d_ - 10) + e_, 95) - rmin;
        s_co[tid] = min(clipi(qj + d_ - 10) + e_, 95) - cmin;
    }
    for (int i=tid; i<RGN2; i+=NT){
        int rr = i/RGN, cc = i - rr*RGN;
        s_goff[i] = min(rmin+rr,95)*WW + min(cmin+cc,95);
    }
    // b1 patch: 4 LDG.128 per patch pixel, scatter into pair layout
    if (tid < 49){
        int a = tid/7, b = tid - 7*a;
        int pp = min(qi+a,95)*WW + min(qj+b,95);
        const float4* b1p = (const float4*)g_b1 + ((size_t)t*HW + pp)*4;
        #pragma unroll
        for (int c=0;c<4;c++){
            float4 v = b1p[c];
            s_b1[(4*c+0)*B1P + a*8 + b] = v.x;
            s_b1[(4*c+1)*B1P + a*8 + b] = v.y;
            s_b1[(4*c+2)*B1P + a*8 + b] = v.z;
            s_b1[(4*c+3)*B1P + a*8 + b] = v.w;
        }
    }
    if (tid >= 64 && tid < 64+CI*7){
        int u = tid - 64, ci = u/7, a = u - 7*ci;
        s_b1[ci*B1P + a*8 + 7] = 0.f;
    }
    __syncthreads();

    // ---- load b3 region: 4 LDG.128 per pixel -> planar fp32 smem
    {
        const float4* b3p = (const float4*)g_b3 + (size_t)t*HW*4;
        for (int i=tid; i<RGN2; i+=NT){
            const float4* p = b3p + (size_t)s_goff[i]*4;
            float4 x0=p[0], x1=p[1], x2=p[2], x3=p[3];
            s_rg[ 0*RGN2+i]=x0.x; s_rg[ 1*RGN2+i]=x0.y; s_rg[ 2*RGN2+i]=x0.z; s_rg[ 3*RGN2+i]=x0.w;
            s_rg[ 4*RGN2+i]=x1.x; s_rg[ 5*RGN2+i]=x1.y; s_rg[ 6*RGN2+i]=x1.z; s_rg[ 7*RGN2+i]=x1.w;
            s_rg[ 8*RGN2+i]=x2.x; s_rg[ 9*RGN2+i]=x2.y; s_rg[10*RGN2+i]=x2.z; s_rg[11*RGN2+i]=x2.w;
            s_rg[12*RGN2+i]=x3.x; s_rg[13*RGN2+i]=x3.y; s_rg[14*RGN2+i]=x3.z; s_rg[15*RGN2+i]=x3.w;
        }
    }
    __syncthreads();

    // ---- stage 1: Q[a][r][dj] via f32x2, weights via LDS.128
    if (tid < 189){
        int r = tid/7, dj0 = (tid%7)*3;
        ull acc2[7][3];
        #pragma unroll
        for (int a=0;a<7;a++){ acc2[a][0]=0ull; acc2[a][1]=0ull; acc2[a][2]=0ull; }

        if (colAffine){
            for (int ci=0; ci<CI; ci++){
                const float* row = s_rg + ci*RGN2 + r*RGN + dj0;
                float win[9];
                #pragma unroll
                for (int j=0;j<9;j++) win[j] = row[j];
                ull wp[9];
                #pragma unroll
                for (int b=0;b<8;b++) wp[b] = pack2(win[b], win[b+1]);
                wp[8] = pack2(win[8], 0.f);
                const ulonglong2* wq2 = (const ulonglong2*)(s_b1 + ci*B1P);
                #pragma unroll
                for (int a=0;a<7;a++){
                    ulonglong2 wab = wq2[a*2], wcd = wq2[a*2+1];
                    #pragma unroll
                    for (int k=0;k<3;k++){
                        fma2(acc2[a][k], wab.x, wp[k]);
                        fma2(acc2[a][k], wab.y, wp[k+2]);
                        fma2(acc2[a][k], wcd.x, wp[k+4]);
                        fma2(acc2[a][k], wcd.y, wp[k+6]);
                    }
                }
            }
        } else {
            int clim = 95 - cmin;
            int cb[3];
            #pragma unroll
            for (int k=0;k<3;k++) cb[k] = s_co[(dj0+k)*7];
            for (int ci=0; ci<CI; ci++){
                const float* row = s_rg + ci*RGN2 + r*RGN;
                ull vp[3][4];
                #pragma unroll
                for (int k=0;k<3;k++){
                    float w0=row[min(cb[k]+0,clim)], w1=row[min(cb[k]+1,clim)];
                    float w2=row[min(cb[k]+2,clim)], w3=row[min(cb[k]+3,clim)];
                    float w4=row[min(cb[k]+4,clim)], w5=row[min(cb[k]+5,clim)];
                    float w6=row[min(cb[k]+6,clim)], w7=row[min(cb[k]+7,clim)];
                    vp[k][0]=pack2(w0,w1); vp[k][1]=pack2(w2,w3);
                    vp[k][2]=pack2(w4,w5); vp[k][3]=pack2(w6,w7);
                }
                const ulonglong2* wq2 = (const ulonglong2*)(s_b1 + ci*B1P);
                #pragma unroll
                for (int a=0;a<7;a++){
                    ulonglong2 wab = wq2[a*2], wcd = wq2[a*2+1];
                    #pragma unroll
                    for (int k=0;k<3;k++){
                        fma2(acc2[a][k], wab.x, vp[k][0]);
                        fma2(acc2[a][k], wab.y, vp[k][1]);
                        fma2(acc2[a][k], wcd.x, vp[k][2]);
                        fma2(acc2[a][k], wcd.y, vp[k][3]);
                    }
                }
            }
        }
        #pragma unroll
        for (int a=0;a<7;a++)
            #pragma unroll
            for (int k=0;k<3;k++)
                s_Q[a*QST + r*WS + dj0 + k] = sum2(acc2[a][k]);
    }
    __syncthreads();

    // ---- prefetch b2 (fp16-packed) chunks 0,1 into uint4 regs
    const uint4* b2p = (const uint4*)g_b2h + (size_t)t*HW*2;
    uint4 pa0, pa1, pb0, pb1;
    {
        size_t g0 = (size_t)s_goff[tid]*2;
        size_t g1 = (size_t)s_goff[tid+256]*2;
        pa0 = b2p[g0]; pa1 = b2p[g0+1];
        pb0 = b2p[g1]; pb1 = b2p[g1+1];
    }

    // ---- stage 2: keys straight into registers
    ull k0, k1;
    {
        int di = tid/WS, dj = tid - WS*di;
        float sc = 0.f;
        #pragma unroll
        for (int a=0;a<7;a++) sc += s_Q[a*QST + s_ro[di*7+a]*WS + dj];
        k0 = ((ull)ordf(sc) << 32) | (unsigned)tid;
        int c1 = tid + 256;
        k1 = 0ull;
        if (c1 < NC){
            int di1 = c1/WS, dj1 = c1 - WS*di1;
            float sc1 = 0.f;
            #pragma unroll
            for (int a=0;a<7;a++) sc1 += s_Q[a*QST + s_ro[di1*7+a]*WS + dj1];
            k1 = ((ull)ordf(sc1) << 32) | (unsigned)c1;
        }
    }
    __syncthreads();

    // ---- bitonic sort 512 descending: regs + shfl, 9 smem steps
    {
        int p1 = tid + 256;
        #pragma unroll
        for (int k=2; k<=32; k<<=1)
            #pragma unroll
            for (int j=k>>1; j; j>>=1){
                k0 = cmpshfl(k0, tid, j, k);
                k1 = cmpshfl(k1, p1,  j, k);
            }
        int tog = 0;
        #pragma unroll
        for (int k=64; k<=512; k<<=1){
            if (k == 512){ if (k0 < k1){ ull tt=k0; k0=k1; k1=tt; } }
            int jstart = (k>>1) > 128 ? 128 : (k>>1);
            for (int j=jstart; j>=32; j>>=1){
                ull* buf = tog ? s_bufB : s_srt;
                buf[tid] = k0; buf[p1] = k1;
                __syncthreads();
                int pt = tid ^ j;
                ull o0 = buf[pt], o1 = buf[pt+256];
                bool km0 = (((tid & j)==0) == (((tid) & k)==0));
                bool km1 = (((tid & j)==0) == (((p1 ) & k)==0));
                k0 = km0 ? (k0>o0?k0:o0) : (k0<o0?k0:o0);
                k1 = km1 ? (k1>o1?k1:o1) : (k1<o1?k1:o1);
                tog ^= 1;
            }
            #pragma unroll
            for (int j=16; j; j>>=1){
                k0 = cmpshfl(k0, tid, j, k);
                k1 = cmpshfl(k1, p1,  j, k);
            }
        }
    }
    if (tid < KSEL) s_srt[tid] = k0;
    __syncthreads();

    // ---- softmax over top-100
    {
        float maxs = iordf((unsigned)(s_srt[0] >> 32));
        if (tid < KSEL){
            ull key = s_srt[tid];
            float sc = iordf((unsigned)(key >> 32));
            s_w[tid]   = expf((sc - maxs)*SCALE);
            s_cid[tid] = (int)(key & 0x1FFu);
        }
        __syncthreads();
        if (tid < 32){
            float s = 0.f;
            for (int k=tid; k<KSEL; k+=32) s += s_w[k];
            #pragma unroll
            for (int o=16;o;o>>=1) s += __shfl_xor_sync(0xffffffffu, s, o);
            if (tid == 0) s_w[KSEL] = 1.f/s;
        }
        __syncthreads();
        if (tid < KSEL) s_w[tid] *= s_w[KSEL];
    }

    // ---- commit prefetched b2 (already fp16-packed) + third chunk + [k][49] offsets
    s_rgH[0*RGN2 + tid] = make_uint2(pa0.x, pa0.y);
    s_rgH[1*RGN2 + tid] = make_uint2(pa0.z, pa0.w);
    s_rgH[2*RGN2 + tid] = make_uint2(pa1.x, pa1.y);
    s_rgH[3*RGN2 + tid] = make_uint2(pa1.z, pa1.w);
    s_rgH[0*RGN2 + tid + 256] = make_uint2(pb0.x, pb0.y);
    s_rgH[1*RGN2 + tid + 256] = make_uint2(pb0.z, pb0.w);
    s_rgH[2*RGN2 + tid + 256] = make_uint2(pb1.x, pb1.y);
    s_rgH[3*RGN2 + tid + 256] = make_uint2(pb1.z, pb1.w);
    if (tid + 512 < RGN2){
        size_t g2 = (size_t)s_goff[tid+512]*2;
        uint4 c0 = b2p[g2], c1v = b2p[g2+1];
        s_rgH[0*RGN2 + tid + 512] = make_uint2(c0.x, c0.y);
        s_rgH[1*RGN2 + tid + 512] = make_uint2(c0.z, c0.w);
        s_rgH[2*RGN2 + tid + 512] = make_uint2(c1v.x, c1v.y);
        s_rgH[3*RGN2 + tid + 512] = make_uint2(c1v.z, c1v.w);
    }
    for (int i=tid; i<KSEL*49; i+=NT){
        int k = i/49, p = i - 49*k;
        int c = s_cid[k];
        int pa = p/7, pb = p - 7*pa;
        s_off[k*49 + p] = s_ro[(c/WS)*7 + pa]*RGN + s_co[(c%WS)*7 + pb];
    }
    __syncthreads();

    // ---- aggregation: 196 threads, per-k: LDS.32 off + LDS.64 fp16 gather
    if (tid < 196){
        int p   = tid % 49;
        int cig = tid / 49;
        const uint2* rg = s_rgH + cig*RGN2;
        float a0=0.f, a1=0.f, a2=0.f, a3=0.f;
        #pragma unroll 2
        for (int k=0; k<KSEL; k+=4){
            float4 w4 = *(const float4*)(s_w + k);
            #pragma unroll
            for (int u=0; u<4; u++){
                float w = (u==0)?w4.x:(u==1)?w4.y:(u==2)?w4.z:w4.w;
                int off = s_off[(k+u)*49 + p];
                uint2 v = rg[off];
                float2 f0 = __half22float2(u2h(v.x));
                float2 f1 = __half22float2(u2h(v.y));
                a0 += w*f0.x; a1 += w*f0.y; a2 += w*f1.x; a3 += w*f1.y;
            }
        }
        int pa = p/7, pb = p - 7*pa;
        int pix = min(qi+pa,95)*WW + min(qj+pb,95);
        float* accb = g_acc + (size_t)(t*CI + cig*4)*HW + pix;
        atomicAdd(accb,        a0);
        atomicAdd(accb +   HW, a1);
        atomicAdd(accb + 2*HW, a2);
        atomicAdd(accb + 3*HW, a3);
    }
}

// ---------------------------------------------------------------- final (2-way split over co)
__global__ void __launch_bounds__(NT) k_final(const float* __restrict__ vid, const float* __restrict__ Ww,
                        const float* __restrict__ Wb, float* __restrict__ out){
    __shared__ __align__(16) float sw[C_*CI + C_];
    for (int i=threadIdx.x; i<C_*CI; i+=NT) sw[i] = Ww[i];
    if (threadIdx.x < C_) sw[C_*CI+threadIdx.x] = Wb[threadIdx.x];
    __syncthreads();

    int sub = blockIdx.x / 144;
    int pid = (blockIdx.x % 144)*NT + threadIdx.x;
    int t = pid / HW, pix = pid % HW;
    int row = pix / WW, col = pix - row*WW;

    int cr = 0, cc = 0;
    #pragma unroll
    for (int a=0;a<7;a++){
        int v = row - a; cr += (v >= 0 && v <= 92 && (v & 3) == 0);
        int u = col - a; cc += (u >= 0 && u <= 92 && (u & 3) == 0);
    }
    if (row == 95) cr += 3;
    if (col == 95) cc += 3;
    float inv = 1.f / (float)(cr*cc);

    float y[CI];
    #pragma unroll
    for (int ci=0;ci<CI;ci++) y[ci] = g_acc[(t*CI+ci)*HW + pix]*inv;

    const float* vp = vid + (size_t)t*C_*HW + pix;
    float*       op = out + (size_t)t*C_*HW + pix;
    int co0 = sub*32;
    #pragma unroll 4
    for (int u=0; u<32; u++){
        int co = co0 + u;
        float s = sw[C_*CI+co];
        #pragma unroll
        for (int g=0; g<4; g++){
            float4 w4 = *(const float4*)(sw + co*CI + 4*g);
            s += w4.x*y[4*g] + w4.y*y[4*g+1] + w4.z*y[4*g+2] + w4.w*y[4*g+3];
        }
        op[co*HW] = vp[co*HW] + s;
    }
}

// ---------------------------------------------------------------- launch
extern "C" void kernel_launch(void* const* d_in, const int* in_sizes, int n_in,
                              void* d_out, int out_size){
    const float* vid  = (const float*)d_in[0];
    const float* g_w  = (const float*)d_in[1];
    const float* g_b  = (const float*)d_in[2];
    const float* th_w = (const float*)d_in[3];
    const float* th_b = (const float*)d_in[4];
    const float* ph_w = (const float*)d_in[5];
    const float* ph_b = (const float*)d_in[6];
    const float* W_w  = (const float*)d_in[7];
    const float* W_b  = (const float*)d_in[8];
    float* out = (float*)d_out;

    const int SMEM = SM_TOT * 4;   // 75132 B
    cudaFuncSetAttribute(k_score, cudaFuncAttributeMaxDynamicSharedMemorySize, SMEM);

    k_proj  <<<4*144, NT>>>(vid, g_w, g_b, th_w, th_b, ph_w, ph_b);
    k_score <<<T_*NQ, NT, SMEM>>>();
    k_final <<<2*144, NT>>>(vid, W_w, W_b, out);
}

// round 12
// speedup vs baseline: 1.4787x; 1.0035x over previous
#include <cuda_runtime.h>
#include <cuda_fp16.h>
#include <math.h>
#include <float.h>

#define T_    4
#define C_    64
#define WW    96
#define HW    9216
#define CI    16
#define PS    7
#define WS    21
#define NQX   24
#define NQ    576
#define NC    441
#define KSEL  100
#define SCALE 10.0f
#define RGN   27
#define RGN2  729
#define NT    256
#define B1P   56
#define QST   (RGN*WS)      // 567

// smem layout (float offsets)
#define SM_B1   0            // 896
#define SM_RG   896          // 11664 (b3 planar fp32; later aliased by fp16 b2)
#define SM_Q    12560        // 3970  (sort buffer B alias + off table)
#define SM_SRT  16530        // u64[512] = 1024 floats (sort buffer A)
#define SM_W    17556        // 104
#define SM_CID  17660        // 100
#define SM_RO   17760        // 147
#define SM_CO   17907        // 147
#define SM_GOFF 18054        // 729
#define SM_TOT  18783        // 75132 bytes

typedef unsigned long long ull;

// scratch: pixel-major layouts. b1/b3: [t*HW][16] fp32 ; b2h: [t*HW][16] fp16
__device__ __align__(16) float    g_b1[(size_t)T_*HW*CI];
__device__ __align__(16) float    g_b3[(size_t)T_*HW*CI];
__device__ __align__(16) unsigned g_b2h[(size_t)T_*HW*8];
__device__ __align__(16) float    g_acc[T_*CI*HW];

__device__ __forceinline__ int clipi(int v){ return min(max(v,0),95); }
__device__ __forceinline__ unsigned ordf(float f){
    unsigned b = __float_as_uint(f);
    return (b & 0x80000000u) ? ~b : (b | 0x80000000u);
}
__device__ __forceinline__ float iordf(unsigned u){
    unsigned b = (u & 0x80000000u) ? (u & 0x7FFFFFFFu) : ~u;
    return __uint_as_float(b);
}
__device__ __forceinline__ ull pack2(float lo, float hi){
    ull r; asm("mov.b64 %0, {%1, %2};" : "=l"(r) : "f"(lo), "f"(hi)); return r;
}
__device__ __forceinline__ void fma2(ull &acc, ull a, ull b){
    asm("fma.rn.f32x2 %0, %1, %2, %0;" : "+l"(acc) : "l"(a), "l"(b));
}
__device__ __forceinline__ float sum2(ull v){
    return __uint_as_float((unsigned)v) + __uint_as_float((unsigned)(v>>32));
}
__device__ __forceinline__ ull cmpshfl(ull v, int p, int j, int k){
    ull o = __shfl_xor_sync(0xffffffffu, v, j);
    bool keepMax = (((p & j)==0) == ((p & k)==0));
    ull mx = v > o ? v : o, mn = v > o ? o : v;
    return keepMax ? mx : mn;
}
__device__ __forceinline__ unsigned h2u(__half2 h){
    return *reinterpret_cast<unsigned*>(&h);
}
__device__ __forceinline__ __half2 u2h(unsigned u){
    return *reinterpret_cast<__half2*>(&u);
}

// ---------------------------------------------------------------- fused 3x conv1x1, 2 pixels/thread, 4-way co split
// grid = 4*72 blocks; chunk of 512 pixels per block (never straddles t)
__global__ void __launch_bounds__(NT) k_proj(const float* __restrict__ vid,
                       const float* __restrict__ gw, const float* __restrict__ gb,
                       const float* __restrict__ tw, const float* __restrict__ tb,
                       const float* __restrict__ pw, const float* __restrict__ pb){
    __shared__ __align__(16) float sw[3*CI*C_ + 3*CI];
    for (int i=threadIdx.x; i<CI*C_; i+=NT){
        sw[i]          = gw[i];
        sw[CI*C_+i]    = tw[i];
        sw[2*CI*C_+i]  = pw[i];
    }
    if (threadIdx.x < CI){
        sw[3*CI*C_         + threadIdx.x] = gb[threadIdx.x];
        sw[3*CI*C_ +   CI  + threadIdx.x] = tb[threadIdx.x];
        sw[3*CI*C_ + 2*CI  + threadIdx.x] = pb[threadIdx.x];
    }

    int gid = blockIdx.x*NT + threadIdx.x;      // [0, 288*256=73728)
    // zero g_acc: 147456 float4, 2 per thread
    ((float4*)g_acc)[gid*2]   = make_float4(0.f,0.f,0.f,0.f);
    ((float4*)g_acc)[gid*2+1] = make_float4(0.f,0.f,0.f,0.f);
    __syncthreads();

    int sub  = blockIdx.x / 72;                 // output channels [4*sub, 4*sub+4)
    int base = (blockIdx.x % 72)*512 + threadIdx.x;   // pixel0 id in [0, T*HW)
    int t = base / HW, pix = base % HW;
    int o0 = sub*4;

    float a1[4], a2[4], a3[4];   // pixel0
    float c1[4], c2[4], c3[4];   // pixel1 (pix+256)
    #pragma unroll
    for (int u=0;u<4;u++){
        a1[u] = sw[3*CI*C_ + o0+u];           c1[u] = a1[u];
        a2[u] = sw[3*CI*C_ + CI + o0+u];      c2[u] = a2[u];
        a3[u] = sw[3*CI*C_ + 2*CI + o0+u];    c3[u] = a3[u];
    }
    const float* vp = vid + (size_t)t*C_*HW + pix;
    #pragma unroll 4
    for (int c=0;c<C_;c+=4){
        float v0 = vp[c*HW],     v1 = vp[(c+1)*HW],     v2 = vp[(c+2)*HW],     v3 = vp[(c+3)*HW];
        float u0 = vp[c*HW+256], u1 = vp[(c+1)*HW+256], u2 = vp[(c+2)*HW+256], u3 = vp[(c+3)*HW+256];
        #pragma unroll
        for (int u=0;u<4;u++){
            int o = o0+u;
            float4 w1 = *(const float4*)(sw + o*C_ + c);
            float4 w2 = *(const float4*)(sw + CI*C_ + o*C_ + c);
            float4 w3 = *(const float4*)(sw + 2*CI*C_ + o*C_ + c);
            a1[u] += v0*w1.x + v1*w1.y + v2*w1.z + v3*w1.w;
            a2[u] += v0*w2.x + v1*w2.y + v2*w2.z + v3*w2.w;
            a3[u] += v0*w3.x + v1*w3.y + v2*w3.z + v3*w3.w;
            c1[u] += u0*w1.x + u1*w1.y + u2*w1.z + u3*w1.w;
            c2[u] += u0*w2.x + u1*w2.y + u2*w2.z + u3*w2.w;
            c3[u] += u0*w3.x + u1*w3.y + u2*w3.z + u3*w3.w;
        }
    }
    // pixel-major writes
    ((float4*)g_b1)[(size_t)base*4 + sub]       = make_float4(a1[0],a1[1],a1[2],a1[3]);
    ((float4*)g_b3)[(size_t)base*4 + sub]       = make_float4(a3[0],a3[1],a3[2],a3[3]);
    ((float4*)g_b1)[(size_t)(base+256)*4 + sub] = make_float4(c1[0],c1[1],c1[2],c1[3]);
    ((float4*)g_b3)[(size_t)(base+256)*4 + sub] = make_float4(c3[0],c3[1],c3[2],c3[3]);
    uint2 h0, h1;
    h0.x = h2u(__floats2half2_rn(a2[0], a2[1]));
    h0.y = h2u(__floats2half2_rn(a2[2], a2[3]));
    h1.x = h2u(__floats2half2_rn(c2[0], c2[1]));
    h1.y = h2u(__floats2half2_rn(c2[2], c2[3]));
    ((uint2*)g_b2h)[(size_t)base*4 + sub]       = h0;
    ((uint2*)g_b2h)[(size_t)(base+256)*4 + sub] = h1;
}

// ---------------------------------------------------------------- main kernel (unchanged from R11)
__global__ void __launch_bounds__(NT, 3) k_score(){
    extern __shared__ float sm[];
    float* s_b1 = sm + SM_B1;
    float* s_rg = sm + SM_RG;
    uint2* s_rgH = (uint2*)(sm + SM_RG);
    float* s_Q  = sm + SM_Q;
    ull*   s_srt = (ull*)(sm + SM_SRT);
    ull*   s_bufB = (ull*)(sm + SM_Q);
    float* s_w   = sm + SM_W;
    int*   s_cid = (int*)(sm + SM_CID);
    int*   s_ro  = (int*)(sm + SM_RO);
    int*   s_co  = (int*)(sm + SM_CO);
    int*   s_goff= (int*)(sm + SM_GOFF);
    int*   s_off = (int*)s_Q;

    int blk = blockIdx.x;
    int t = blk / NQ, q = blk % NQ;
    int qi = (q / NQX)*4, qj = (q % NQX)*4;
    int tid = threadIdx.x;

    int rmin = max(qi-10, 0), cmin = max(qj-10, 0);
    bool colAffine = (qj >= 12 && qj <= 76);

    // ---- tables
    if (tid < 147){
        int d_ = tid/7, e_ = tid%7;
        s_ro[tid] = min(clipi(qi + d_ - 10) + e_, 95) - rmin;
        s_co[tid] = min(clipi(qj + d_ - 10) + e_, 95) - cmin;
    }
    for (int i=tid; i<RGN2; i+=NT){
        int rr = i/RGN, cc = i - rr*RGN;
        s_goff[i] = min(rmin+rr,95)*WW + min(cmin+cc,95);
    }
    // b1 patch: 4 LDG.128 per patch pixel, scatter into pair layout
    if (tid < 49){
        int a = tid/7, b = tid - 7*a;
        int pp = min(qi+a,95)*WW + min(qj+b,95);
        const float4* b1p = (const float4*)g_b1 + ((size_t)t*HW + pp)*4;
        #pragma unroll
        for (int c=0;c<4;c++){
            float4 v = b1p[c];
            s_b1[(4*c+0)*B1P + a*8 + b] = v.x;
            s_b1[(4*c+1)*B1P + a*8 + b] = v.y;
            s_b1[(4*c+2)*B1P + a*8 + b] = v.z;
            s_b1[(4*c+3)*B1P + a*8 + b] = v.w;
        }
    }
    if (tid >= 64 && tid < 64+CI*7){
        int u = tid - 64, ci = u/7, a = u - 7*ci;
        s_b1[ci*B1P + a*8 + 7] = 0.f;
    }
    __syncthreads();

    // ---- load b3 region: 4 LDG.128 per pixel -> planar fp32 smem
    {
        const float4* b3p = (const float4*)g_b3 + (size_t)t*HW*4;
        for (int i=tid; i<RGN2; i+=NT){
            const float4* p = b3p + (size_t)s_goff[i]*4;
            float4 x0=p[0], x1=p[1], x2=p[2], x3=p[3];
            s_rg[ 0*RGN2+i]=x0.x; s_rg[ 1*RGN2+i]=x0.y; s_rg[ 2*RGN2+i]=x0.z; s_rg[ 3*RGN2+i]=x0.w;
            s_rg[ 4*RGN2+i]=x1.x; s_rg[ 5*RGN2+i]=x1.y; s_rg[ 6*RGN2+i]=x1.z; s_rg[ 7*RGN2+i]=x1.w;
            s_rg[ 8*RGN2+i]=x2.x; s_rg[ 9*RGN2+i]=x2.y; s_rg[10*RGN2+i]=x2.z; s_rg[11*RGN2+i]=x2.w;
            s_rg[12*RGN2+i]=x3.x; s_rg[13*RGN2+i]=x3.y; s_rg[14*RGN2+i]=x3.z; s_rg[15*RGN2+i]=x3.w;
        }
    }
    __syncthreads();

    // ---- stage 1: Q[a][r][dj] via f32x2, weights via LDS.128
    if (tid < 189){
        int r = tid/7, dj0 = (tid%7)*3;
        ull acc2[7][3];
        #pragma unroll
        for (int a=0;a<7;a++){ acc2[a][0]=0ull; acc2[a][1]=0ull; acc2[a][2]=0ull; }

        if (colAffine){
            for (int ci=0; ci<CI; ci++){
                const float* row = s_rg + ci*RGN2 + r*RGN + dj0;
                float win[9];
                #pragma unroll
                for (int j=0;j<9;j++) win[j] = row[j];
                ull wp[9];
                #pragma unroll
                for (int b=0;b<8;b++) wp[b] = pack2(win[b], win[b+1]);
                wp[8] = pack2(win[8], 0.f);
                const ulonglong2* wq2 = (const ulonglong2*)(s_b1 + ci*B1P);
                #pragma unroll
                for (int a=0;a<7;a++){
                    ulonglong2 wab = wq2[a*2], wcd = wq2[a*2+1];
                    #pragma unroll
                    for (int k=0;k<3;k++){
                        fma2(acc2[a][k], wab.x, wp[k]);
                        fma2(acc2[a][k], wab.y, wp[k+2]);
                        fma2(acc2[a][k], wcd.x, wp[k+4]);
                        fma2(acc2[a][k], wcd.y, wp[k+6]);
                    }
                }
            }
        } else {
            int clim = 95 - cmin;
            int cb[3];
            #pragma unroll
            for (int k=0;k<3;k++) cb[k] = s_co[(dj0+k)*7];
            for (int ci=0; ci<CI; ci++){
                const float* row = s_rg + ci*RGN2 + r*RGN;
                ull vp[3][4];
                #pragma unroll
                for (int k=0;k<3;k++){
                    float w0=row[min(cb[k]+0,clim)], w1=row[min(cb[k]+1,clim)];
                    float w2=row[min(cb[k]+2,clim)], w3=row[min(cb[k]+3,clim)];
                    float w4=row[min(cb[k]+4,clim)], w5=row[min(cb[k]+5,clim)];
                    float w6=row[min(cb[k]+6,clim)], w7=row[min(cb[k]+7,clim)];
                    vp[k][0]=pack2(w0,w1); vp[k][1]=pack2(w2,w3);
                    vp[k][2]=pack2(w4,w5); vp[k][3]=pack2(w6,w7);
                }
                const ulonglong2* wq2 = (const ulonglong2*)(s_b1 + ci*B1P);
                #pragma unroll
                for (int a=0;a<7;a++){
                    ulonglong2 wab = wq2[a*2], wcd = wq2[a*2+1];
                    #pragma unroll
                    for (int k=0;k<3;k++){
                        fma2(acc2[a][k], wab.x, vp[k][0]);
                        fma2(acc2[a][k], wab.y, vp[k][1]);
                        fma2(acc2[a][k], wcd.x, vp[k][2]);
                        fma2(acc2[a][k], wcd.y, vp[k][3]);
                    }
                }
            }
        }
        #pragma unroll
        for (int a=0;a<7;a++)
            #pragma unroll
            for (int k=0;k<3;k++)
                s_Q[a*QST + r*WS + dj0 + k] = sum2(acc2[a][k]);
    }
    __syncthreads();

    // ---- prefetch b2 (fp16-packed) chunks 0,1 into uint4 regs
    const uint4* b2p = (const uint4*)g_b2h + (size_t)t*HW*2;
    uint4 pa0, pa1, pb0, pb1;
    {
        size_t g0 = (size_t)s_goff[tid]*2;
        size_t g1 = (size_t)s_goff[tid+256]*2;
        pa0 = b2p[g0]; pa1 = b2p[g0+1];
        pb0 = b2p[g1]; pb1 = b2p[g1+1];
    }

    // ---- stage 2: keys straight into registers
    ull k0, k1;
    {
        int di = tid/WS, dj = tid - WS*di;
        float sc = 0.f;
        #pragma unroll
        for (int a=0;a<7;a++) sc += s_Q[a*QST + s_ro[di*7+a]*WS + dj];
        k0 = ((ull)ordf(sc) << 32) | (unsigned)tid;
        int c1 = tid + 256;
        k1 = 0ull;
        if (c1 < NC){
            int di1 = c1/WS, dj1 = c1 - WS*di1;
            float sc1 = 0.f;
            #pragma unroll
            for (int a=0;a<7;a++) sc1 += s_Q[a*QST + s_ro[di1*7+a]*WS + dj1];
            k1 = ((ull)ordf(sc1) << 32) | (unsigned)c1;
        }
    }
    __syncthreads();

    // ---- bitonic sort 512 descending: regs + shfl, 9 smem steps
    {
        int p1 = tid + 256;
        #pragma unroll
        for (int k=2; k<=32; k<<=1)
            #pragma unroll
            for (int j=k>>1; j; j>>=1){
                k0 = cmpshfl(k0, tid, j, k);
                k1 = cmpshfl(k1, p1,  j, k);
            }
        int tog = 0;
        #pragma unroll
        for (int k=64; k<=512; k<<=1){
            if (k == 512){ if (k0 < k1){ ull tt=k0; k0=k1; k1=tt; } }
            int jstart = (k>>1) > 128 ? 128 : (k>>1);
            for (int j=jstart; j>=32; j>>=1){
                ull* buf = tog ? s_bufB : s_srt;
                buf[tid] = k0; buf[p1] = k1;
                __syncthreads();
                int pt = tid ^ j;
                ull o0 = buf[pt], o1 = buf[pt+256];
                bool km0 = (((tid & j)==0) == (((tid) & k)==0));
                bool km1 = (((tid & j)==0) == (((p1 ) & k)==0));
                k0 = km0 ? (k0>o0?k0:o0) : (k0<o0?k0:o0);
                k1 = km1 ? (k1>o1?k1:o1) : (k1<o1?k1:o1);
                tog ^= 1;
            }
            #pragma unroll
            for (int j=16; j; j>>=1){
                k0 = cmpshfl(k0, tid, j, k);
                k1 = cmpshfl(k1, p1,  j, k);
            }
        }
    }
    if (tid < KSEL) s_srt[tid] = k0;
    __syncthreads();

    // ---- softmax over top-100
    {
        float maxs = iordf((unsigned)(s_srt[0] >> 32));
        if (tid < KSEL){
            ull key = s_srt[tid];
            float sc = iordf((unsigned)(key >> 32));
            s_w[tid]   = expf((sc - maxs)*SCALE);
            s_cid[tid] = (int)(key & 0x1FFu);
        }
        __syncthreads();
        if (tid < 32){
            float s = 0.f;
            for (int k=tid; k<KSEL; k+=32) s += s_w[k];
            #pragma unroll
            for (int o=16;o;o>>=1) s += __shfl_xor_sync(0xffffffffu, s, o);
            if (tid == 0) s_w[KSEL] = 1.f/s;
        }
        __syncthreads();
        if (tid < KSEL) s_w[tid] *= s_w[KSEL];
    }

    // ---- commit prefetched b2 (already fp16-packed) + third chunk + [k][49] offsets
    s_rgH[0*RGN2 + tid] = make_uint2(pa0.x, pa0.y);
    s_rgH[1*RGN2 + tid] = make_uint2(pa0.z, pa0.w);
    s_rgH[2*RGN2 + tid] = make_uint2(pa1.x, pa1.y);
    s_rgH[3*RGN2 + tid] = make_uint2(pa1.z, pa1.w);
    s_rgH[0*RGN2 + tid + 256] = make_uint2(pb0.x, pb0.y);
    s_rgH[1*RGN2 + tid + 256] = make_uint2(pb0.z, pb0.w);
    s_rgH[2*RGN2 + tid + 256] = make_uint2(pb1.x, pb1.y);
    s_rgH[3*RGN2 + tid + 256] = make_uint2(pb1.z, pb1.w);
    if (tid + 512 < RGN2){
        size_t g2 = (size_t)s_goff[tid+512]*2;
        uint4 c0 = b2p[g2], c1v = b2p[g2+1];
        s_rgH[0*RGN2 + tid + 512] = make_uint2(c0.x, c0.y);
        s_rgH[1*RGN2 + tid + 512] = make_uint2(c0.z, c0.w);
        s_rgH[2*RGN2 + tid + 512] = make_uint2(c1v.x, c1v.y);
        s_rgH[3*RGN2 + tid + 512] = make_uint2(c1v.z, c1v.w);
    }
    for (int i=tid; i<KSEL*49; i+=NT){
        int k = i/49, p = i - 49*k;
        int c = s_cid[k];
        int pa = p/7, pb = p - 7*pa;
        s_off[k*49 + p] = s_ro[(c/WS)*7 + pa]*RGN + s_co[(c%WS)*7 + pb];
    }
    __syncthreads();

    // ---- aggregation: 196 threads, per-k: LDS.32 off + LDS.64 fp16 gather
    if (tid < 196){
        int p   = tid % 49;
        int cig = tid / 49;
        const uint2* rg = s_rgH + cig*RGN2;
        float a0=0.f, a1=0.f, a2=0.f, a3=0.f;
        #pragma unroll 2
        for (int k=0; k<KSEL; k+=4){
            float4 w4 = *(const float4*)(s_w + k);
            #pragma unroll
            for (int u=0; u<4; u++){
                float w = (u==0)?w4.x:(u==1)?w4.y:(u==2)?w4.z:w4.w;
                int off = s_off[(k+u)*49 + p];
                uint2 v = rg[off];
                float2 f0 = __half22float2(u2h(v.x));
                float2 f1 = __half22float2(u2h(v.y));
                a0 += w*f0.x; a1 += w*f0.y; a2 += w*f1.x; a3 += w*f1.y;
            }
        }
        int pa = p/7, pb = p - 7*pa;
        int pix = min(qi+pa,95)*WW + min(qj+pb,95);
        float* accb = g_acc + (size_t)(t*CI + cig*4)*HW + pix;
        atomicAdd(accb,        a0);
        atomicAdd(accb +   HW, a1);
        atomicAdd(accb + 2*HW, a2);
        atomicAdd(accb + 3*HW, a3);
    }
}

// ---------------------------------------------------------------- final: 2 pixels/thread, 2-way co split
// grid = 2*72 blocks; chunk of 512 pixels per block
__global__ void __launch_bounds__(NT) k_final(const float* __restrict__ vid, const float* __restrict__ Ww,
                        const float* __restrict__ Wb, float* __restrict__ out){
    __shared__ __align__(16) float sw[C_*CI + C_];
    for (int i=threadIdx.x; i<C_*CI; i+=NT) sw[i] = Ww[i];
    if (threadIdx.x < C_) sw[C_*CI+threadIdx.x] = Wb[threadIdx.x];
    __syncthreads();

    int sub  = blockIdx.x / 72;                 // co range [32*sub, 32*sub+32)
    int base = (blockIdx.x % 72)*512 + threadIdx.x;
    int t = base / HW, pix = base % HW;

    // analytic overlap counts for both pixels
    float inv0, inv1;
    #pragma unroll
    for (int pp=0; pp<2; pp++){
        int px = pix + pp*256;
        int row = px / WW, col = px - row*WW;
        int cr = 0, cc = 0;
        #pragma unroll
        for (int a=0;a<7;a++){
            int v = row - a; cr += (v >= 0 && v <= 92 && (v & 3) == 0);
            int u = col - a; cc += (u >= 0 && u <= 92 && (u & 3) == 0);
        }
        if (row == 95) cr += 3;
        if (col == 95) cc += 3;
        float inv = 1.f / (float)(cr*cc);
        if (pp == 0) inv0 = inv; else inv1 = inv;
    }

    float y0[CI], y1[CI];
    #pragma unroll
    for (int ci=0;ci<CI;ci++){
        y0[ci] = g_acc[(t*CI+ci)*HW + pix]       * inv0;
        y1[ci] = g_acc[(t*CI+ci)*HW + pix + 256] * inv1;
    }

    const float* vp = vid + (size_t)t*C_*HW + pix;
    float*       op = out + (size_t)t*C_*HW + pix;
    int co0 = sub*32;
    #pragma unroll 4
    for (int u=0; u<32; u++){
        int co = co0 + u;
        float bias = sw[C_*CI+co];
        float s0 = bias, s1 = bias;
        #pragma unroll
        for (int g=0; g<4; g++){
            float4 w4 = *(const float4*)(sw + co*CI + 4*g);
            s0 += w4.x*y0[4*g] + w4.y*y0[4*g+1] + w4.z*y0[4*g+2] + w4.w*y0[4*g+3];
            s1 += w4.x*y1[4*g] + w4.y*y1[4*g+1] + w4.z*y1[4*g+2] + w4.w*y1[4*g+3];
        }
        op[co*HW]       = vp[co*HW]       + s0;
        op[co*HW + 256] = vp[co*HW + 256] + s1;
    }
}

// ---------------------------------------------------------------- launch
extern "C" void kernel_launch(void* const* d_in, const int* in_sizes, int n_in,
                              void* d_out, int out_size){
    const float* vid  = (const float*)d_in[0];
    const float* g_w  = (const float*)d_in[1];
    const float* g_b  = (const float*)d_in[2];
    const float* th_w = (const float*)d_in[3];
    const float* th_b = (const float*)d_in[4];
    const float* ph_w = (const float*)d_in[5];
    const float* ph_b = (const float*)d_in[6];
    const float* W_w  = (const float*)d_in[7];
    const float* W_b  = (const float*)d_in[8];
    float* out = (float*)d_out;

    const int SMEM = SM_TOT * 4;   // 75132 B
    cudaFuncSetAttribute(k_score, cudaFuncAttributeMaxDynamicSharedMemorySize, SMEM);

    k_proj  <<<4*72, NT>>>(vid, g_w, g_b, th_w, th_b, ph_w, ph_b);
    k_score <<<T_*NQ, NT, SMEM>>>();
    k_final <<<2*72, NT>>>(vid, W_w, W_b, out);
}

// round 13
// speedup vs baseline: 1.4825x; 1.0026x over previous
#include <cuda_runtime.h>
#include <cuda_fp16.h>
#include <math.h>
#include <float.h>

#define T_    4
#define C_    64
#define WW    96
#define HW    9216
#define CI    16
#define PS    7
#define WS    21
#define NQX   24
#define NQ    576
#define NC    441
#define KSEL  100
#define SCALE 10.0f
#define RGN   27
#define RGN2  729
#define NT    256
#define NTC   128           // conv kernels block size
#define B1P   56
#define QST   (RGN*WS)      // 567

// smem layout (float offsets)
#define SM_B1   0            // 896
#define SM_RG   896          // 11664 (b3 planar fp32; later aliased by fp16 b2)
#define SM_Q    12560        // 3970  (sort buffer B alias + off table)
#define SM_SRT  16530        // u64[512] = 1024 floats (sort buffer A)
#define SM_W    17556        // 104
#define SM_CID  17660        // 100
#define SM_RO   17760        // 147
#define SM_CO   17907        // 147
#define SM_GOFF 18054        // 729
#define SM_TOT  18783        // 75132 bytes

typedef unsigned long long ull;

// scratch: pixel-major layouts. b1/b3: [t*HW][16] fp32 ; b2h: [t*HW][16] fp16
__device__ __align__(16) float    g_b1[(size_t)T_*HW*CI];
__device__ __align__(16) float    g_b3[(size_t)T_*HW*CI];
__device__ __align__(16) unsigned g_b2h[(size_t)T_*HW*8];
__device__ __align__(16) float    g_acc[T_*CI*HW];

__device__ __forceinline__ int clipi(int v){ return min(max(v,0),95); }
__device__ __forceinline__ unsigned ordf(float f){
    unsigned b = __float_as_uint(f);
    return (b & 0x80000000u) ? ~b : (b | 0x80000000u);
}
__device__ __forceinline__ float iordf(unsigned u){
    unsigned b = (u & 0x80000000u) ? (u & 0x7FFFFFFFu) : ~u;
    return __uint_as_float(b);
}
__device__ __forceinline__ ull pack2(float lo, float hi){
    ull r; asm("mov.b64 %0, {%1, %2};" : "=l"(r) : "f"(lo), "f"(hi)); return r;
}
__device__ __forceinline__ void fma2(ull &acc, ull a, ull b){
    asm("fma.rn.f32x2 %0, %1, %2, %0;" : "+l"(acc) : "l"(a), "l"(b));
}
__device__ __forceinline__ float sum2(ull v){
    return __uint_as_float((unsigned)v) + __uint_as_float((unsigned)(v>>32));
}
__device__ __forceinline__ ull cmpshfl(ull v, int p, int j, int k){
    ull o = __shfl_xor_sync(0xffffffffu, v, j);
    bool keepMax = (((p & j)==0) == ((p & k)==0));
    ull mx = v > o ? v : o, mn = v > o ? o : v;
    return keepMax ? mx : mn;
}
__device__ __forceinline__ unsigned h2u(__half2 h){
    return *reinterpret_cast<unsigned*>(&h);
}
__device__ __forceinline__ __half2 u2h(unsigned u){
    return *reinterpret_cast<__half2*>(&u);
}

// ---------------------------------------------------------------- fused 3x conv1x1, 2 pixels/thread, 128-thr blocks
// grid = 4*144 blocks; each block: 256-pixel chunk, 4 output channels
__global__ void __launch_bounds__(NTC) k_proj(const float* __restrict__ vid,
                       const float* __restrict__ gw, const float* __restrict__ gb,
                       const float* __restrict__ tw, const float* __restrict__ tb,
                       const float* __restrict__ pw, const float* __restrict__ pb){
    __shared__ __align__(16) float sw[3*CI*C_ + 3*CI];
    for (int i=threadIdx.x; i<CI*C_; i+=NTC){
        sw[i]          = gw[i];
        sw[CI*C_+i]    = tw[i];
        sw[2*CI*C_+i]  = pw[i];
    }
    if (threadIdx.x < CI){
        sw[3*CI*C_         + threadIdx.x] = gb[threadIdx.x];
        sw[3*CI*C_ +   CI  + threadIdx.x] = tb[threadIdx.x];
        sw[3*CI*C_ + 2*CI  + threadIdx.x] = pb[threadIdx.x];
    }

    int gid = blockIdx.x*NTC + threadIdx.x;     // [0, 576*128=73728)
    // zero g_acc: 147456 float4, 2 per thread
    ((float4*)g_acc)[gid*2]   = make_float4(0.f,0.f,0.f,0.f);
    ((float4*)g_acc)[gid*2+1] = make_float4(0.f,0.f,0.f,0.f);
    __syncthreads();

    int sub  = blockIdx.x / 144;                // output channels [4*sub, 4*sub+4)
    int base = (blockIdx.x % 144)*256 + threadIdx.x;   // pixel0 id in [0, T*HW)
    int t = base / HW, pix = base % HW;
    int o0 = sub*4;

    float a1[4], a2[4], a3[4];   // pixel0
    float c1[4], c2[4], c3[4];   // pixel1 (pix+128)
    #pragma unroll
    for (int u=0;u<4;u++){
        a1[u] = sw[3*CI*C_ + o0+u];           c1[u] = a1[u];
        a2[u] = sw[3*CI*C_ + CI + o0+u];      c2[u] = a2[u];
        a3[u] = sw[3*CI*C_ + 2*CI + o0+u];    c3[u] = a3[u];
    }
    const float* vp = vid + (size_t)t*C_*HW + pix;
    #pragma unroll 4
    for (int c=0;c<C_;c+=4){
        float v0 = vp[c*HW],     v1 = vp[(c+1)*HW],     v2 = vp[(c+2)*HW],     v3 = vp[(c+3)*HW];
        float u0 = vp[c*HW+128], u1 = vp[(c+1)*HW+128], u2 = vp[(c+2)*HW+128], u3 = vp[(c+3)*HW+128];
        #pragma unroll
        for (int u=0;u<4;u++){
            int o = o0+u;
            float4 w1 = *(const float4*)(sw + o*C_ + c);
            float4 w2 = *(const float4*)(sw + CI*C_ + o*C_ + c);
            float4 w3 = *(const float4*)(sw + 2*CI*C_ + o*C_ + c);
            a1[u] += v0*w1.x + v1*w1.y + v2*w1.z + v3*w1.w;
            a2[u] += v0*w2.x + v1*w2.y + v2*w2.z + v3*w2.w;
            a3[u] += v0*w3.x + v1*w3.y + v2*w3.z + v3*w3.w;
            c1[u] += u0*w1.x + u1*w1.y + u2*w1.z + u3*w1.w;
            c2[u] += u0*w2.x + u1*w2.y + u2*w2.z + u3*w2.w;
            c3[u] += u0*w3.x + u1*w3.y + u2*w3.z + u3*w3.w;
        }
    }
    // pixel-major writes
    ((float4*)g_b1)[(size_t)base*4 + sub]       = make_float4(a1[0],a1[1],a1[2],a1[3]);
    ((float4*)g_b3)[(size_t)base*4 + sub]       = make_float4(a3[0],a3[1],a3[2],a3[3]);
    ((float4*)g_b1)[(size_t)(base+128)*4 + sub] = make_float4(c1[0],c1[1],c1[2],c1[3]);
    ((float4*)g_b3)[(size_t)(base+128)*4 + sub] = make_float4(c3[0],c3[1],c3[2],c3[3]);
    uint2 h0, h1;
    h0.x = h2u(__floats2half2_rn(a2[0], a2[1]));
    h0.y = h2u(__floats2half2_rn(a2[2], a2[3]));
    h1.x = h2u(__floats2half2_rn(c2[0], c2[1]));
    h1.y = h2u(__floats2half2_rn(c2[2], c2[3]));
    ((uint2*)g_b2h)[(size_t)base*4 + sub]       = h0;
    ((uint2*)g_b2h)[(size_t)(base+128)*4 + sub] = h1;
}

// ---------------------------------------------------------------- main kernel (unchanged)
__global__ void __launch_bounds__(NT, 3) k_score(){
    extern __shared__ float sm[];
    float* s_b1 = sm + SM_B1;
    float* s_rg = sm + SM_RG;
    uint2* s_rgH = (uint2*)(sm + SM_RG);
    float* s_Q  = sm + SM_Q;
    ull*   s_srt = (ull*)(sm + SM_SRT);
    ull*   s_bufB = (ull*)(sm + SM_Q);
    float* s_w   = sm + SM_W;
    int*   s_cid = (int*)(sm + SM_CID);
    int*   s_ro  = (int*)(sm + SM_RO);
    int*   s_co  = (int*)(sm + SM_CO);
    int*   s_goff= (int*)(sm + SM_GOFF);
    int*   s_off = (int*)s_Q;

    int blk = blockIdx.x;
    int t = blk / NQ, q = blk % NQ;
    int qi = (q / NQX)*4, qj = (q % NQX)*4;
    int tid = threadIdx.x;

    int rmin = max(qi-10, 0), cmin = max(qj-10, 0);
    bool colAffine = (qj >= 12 && qj <= 76);

    // ---- tables
    if (tid < 147){
        int d_ = tid/7, e_ = tid%7;
        s_ro[tid] = min(clipi(qi + d_ - 10) + e_, 95) - rmin;
        s_co[tid] = min(clipi(qj + d_ - 10) + e_, 95) - cmin;
    }
    for (int i=tid; i<RGN2; i+=NT){
        int rr = i/RGN, cc = i - rr*RGN;
        s_goff[i] = min(rmin+rr,95)*WW + min(cmin+cc,95);
    }
    // b1 patch: 4 LDG.128 per patch pixel, scatter into pair layout
    if (tid < 49){
        int a = tid/7, b = tid - 7*a;
        int pp = min(qi+a,95)*WW + min(qj+b,95);
        const float4* b1p = (const float4*)g_b1 + ((size_t)t*HW + pp)*4;
        #pragma unroll
        for (int c=0;c<4;c++){
            float4 v = b1p[c];
            s_b1[(4*c+0)*B1P + a*8 + b] = v.x;
            s_b1[(4*c+1)*B1P + a*8 + b] = v.y;
            s_b1[(4*c+2)*B1P + a*8 + b] = v.z;
            s_b1[(4*c+3)*B1P + a*8 + b] = v.w;
        }
    }
    if (tid >= 64 && tid < 64+CI*7){
        int u = tid - 64, ci = u/7, a = u - 7*ci;
        s_b1[ci*B1P + a*8 + 7] = 0.f;
    }
    __syncthreads();

    // ---- load b3 region: 4 LDG.128 per pixel -> planar fp32 smem
    {
        const float4* b3p = (const float4*)g_b3 + (size_t)t*HW*4;
        for (int i=tid; i<RGN2; i+=NT){
            const float4* p = b3p + (size_t)s_goff[i]*4;
            float4 x0=p[0], x1=p[1], x2=p[2], x3=p[3];
            s_rg[ 0*RGN2+i]=x0.x; s_rg[ 1*RGN2+i]=x0.y; s_rg[ 2*RGN2+i]=x0.z; s_rg[ 3*RGN2+i]=x0.w;
            s_rg[ 4*RGN2+i]=x1.x; s_rg[ 5*RGN2+i]=x1.y; s_rg[ 6*RGN2+i]=x1.z; s_rg[ 7*RGN2+i]=x1.w;
            s_rg[ 8*RGN2+i]=x2.x; s_rg[ 9*RGN2+i]=x2.y; s_rg[10*RGN2+i]=x2.z; s_rg[11*RGN2+i]=x2.w;
            s_rg[12*RGN2+i]=x3.x; s_rg[13*RGN2+i]=x3.y; s_rg[14*RGN2+i]=x3.z; s_rg[15*RGN2+i]=x3.w;
        }
    }
    __syncthreads();

    // ---- stage 1: Q[a][r][dj] via f32x2, weights via LDS.128
    if (tid < 189){
        int r = tid/7, dj0 = (tid%7)*3;
        ull acc2[7][3];
        #pragma unroll
        for (int a=0;a<7;a++){ acc2[a][0]=0ull; acc2[a][1]=0ull; acc2[a][2]=0ull; }

        if (colAffine){
            for (int ci=0; ci<CI; ci++){
                const float* row = s_rg + ci*RGN2 + r*RGN + dj0;
                float win[9];
                #pragma unroll
                for (int j=0;j<9;j++) win[j] = row[j];
                ull wp[9];
                #pragma unroll
                for (int b=0;b<8;b++) wp[b] = pack2(win[b], win[b+1]);
                wp[8] = pack2(win[8], 0.f);
                const ulonglong2* wq2 = (const ulonglong2*)(s_b1 + ci*B1P);
                #pragma unroll
                for (int a=0;a<7;a++){
                    ulonglong2 wab = wq2[a*2], wcd = wq2[a*2+1];
                    #pragma unroll
                    for (int k=0;k<3;k++){
                        fma2(acc2[a][k], wab.x, wp[k]);
                        fma2(acc2[a][k], wab.y, wp[k+2]);
                        fma2(acc2[a][k], wcd.x, wp[k+4]);
                        fma2(acc2[a][k], wcd.y, wp[k+6]);
                    }
                }
            }
        } else {
            int clim = 95 - cmin;
            int cb[3];
            #pragma unroll
            for (int k=0;k<3;k++) cb[k] = s_co[(dj0+k)*7];
            for (int ci=0; ci<CI; ci++){
                const float* row = s_rg + ci*RGN2 + r*RGN;
                ull vp[3][4];
                #pragma unroll
                for (int k=0;k<3;k++){
                    float w0=row[min(cb[k]+0,clim)], w1=row[min(cb[k]+1,clim)];
                    float w2=row[min(cb[k]+2,clim)], w3=row[min(cb[k]+3,clim)];
                    float w4=row[min(cb[k]+4,clim)], w5=row[min(cb[k]+5,clim)];
                    float w6=row[min(cb[k]+6,clim)], w7=row[min(cb[k]+7,clim)];
                    vp[k][0]=pack2(w0,w1); vp[k][1]=pack2(w2,w3);
                    vp[k][2]=pack2(w4,w5); vp[k][3]=pack2(w6,w7);
                }
                const ulonglong2* wq2 = (const ulonglong2*)(s_b1 + ci*B1P);
                #pragma unroll
                for (int a=0;a<7;a++){
                    ulonglong2 wab = wq2[a*2], wcd = wq2[a*2+1];
                    #pragma unroll
                    for (int k=0;k<3;k++){
                        fma2(acc2[a][k], wab.x, vp[k][0]);
                        fma2(acc2[a][k], wab.y, vp[k][1]);
                        fma2(acc2[a][k], wcd.x, vp[k][2]);
                        fma2(acc2[a][k], wcd.y, vp[k][3]);
                    }
                }
            }
        }
        #pragma unroll
        for (int a=0;a<7;a++)
            #pragma unroll
            for (int k=0;k<3;k++)
                s_Q[a*QST + r*WS + dj0 + k] = sum2(acc2[a][k]);
    }
    __syncthreads();

    // ---- prefetch b2 (fp16-packed) chunks 0,1 into uint4 regs
    const uint4* b2p = (const uint4*)g_b2h + (size_t)t*HW*2;
    uint4 pa0, pa1, pb0, pb1;
    {
        size_t g0 = (size_t)s_goff[tid]*2;
        size_t g1 = (size_t)s_goff[tid+256]*2;
        pa0 = b2p[g0]; pa1 = b2p[g0+1];
        pb0 = b2p[g1]; pb1 = b2p[g1+1];
    }

    // ---- stage 2: keys straight into registers
    ull k0, k1;
    {
        int di = tid/WS, dj = tid - WS*di;
        float sc = 0.f;
        #pragma unroll
        for (int a=0;a<7;a++) sc += s_Q[a*QST + s_ro[di*7+a]*WS + dj];
        k0 = ((ull)ordf(sc) << 32) | (unsigned)tid;
        int c1 = tid + 256;
        k1 = 0ull;
        if (c1 < NC){
            int di1 = c1/WS, dj1 = c1 - WS*di1;
            float sc1 = 0.f;
            #pragma unroll
            for (int a=0;a<7;a++) sc1 += s_Q[a*QST + s_ro[di1*7+a]*WS + dj1];
            k1 = ((ull)ordf(sc1) << 32) | (unsigned)c1;
        }
    }
    __syncthreads();

    // ---- bitonic sort 512 descending: regs + shfl, 9 smem steps
    {
        int p1 = tid + 256;
        #pragma unroll
        for (int k=2; k<=32; k<<=1)
            #pragma unroll
            for (int j=k>>1; j; j>>=1){
                k0 = cmpshfl(k0, tid, j, k);
                k1 = cmpshfl(k1, p1,  j, k);
            }
        int tog = 0;
        #pragma unroll
        for (int k=64; k<=512; k<<=1){
            if (k == 512){ if (k0 < k1){ ull tt=k0; k0=k1; k1=tt; } }
            int jstart = (k>>1) > 128 ? 128 : (k>>1);
            for (int j=jstart; j>=32; j>>=1){
                ull* buf = tog ? s_bufB : s_srt;
                buf[tid] = k0; buf[p1] = k1;
                __syncthreads();
                int pt = tid ^ j;
                ull o0 = buf[pt], o1 = buf[pt+256];
                bool km0 = (((tid & j)==0) == (((tid) & k)==0));
                bool km1 = (((tid & j)==0) == (((p1 ) & k)==0));
                k0 = km0 ? (k0>o0?k0:o0) : (k0<o0?k0:o0);
                k1 = km1 ? (k1>o1?k1:o1) : (k1<o1?k1:o1);
                tog ^= 1;
            }
            #pragma unroll
            for (int j=16; j; j>>=1){
                k0 = cmpshfl(k0, tid, j, k);
                k1 = cmpshfl(k1, p1,  j, k);
            }
        }
    }
    if (tid < KSEL) s_srt[tid] = k0;
    __syncthreads();

    // ---- softmax over top-100
    {
        float maxs = iordf((unsigned)(s_srt[0] >> 32));
        if (tid < KSEL){
            ull key = s_srt[tid];
            float sc = iordf((unsigned)(key >> 32));
            s_w[tid]   = expf((sc - maxs)*SCALE);
            s_cid[tid] = (int)(key & 0x1FFu);
        }
        __syncthreads();
        if (tid < 32){
            float s = 0.f;
            for (int k=tid; k<KSEL; k+=32) s += s_w[k];
            #pragma unroll
            for (int o=16;o;o>>=1) s += __shfl_xor_sync(0xffffffffu, s, o);
            if (tid == 0) s_w[KSEL] = 1.f/s;
        }
        __syncthreads();
        if (tid < KSEL) s_w[tid] *= s_w[KSEL];
    }

    // ---- commit prefetched b2 (already fp16-packed) + third chunk + [k][49] offsets
    s_rgH[0*RGN2 + tid] = make_uint2(pa0.x, pa0.y);
    s_rgH[1*RGN2 + tid] = make_uint2(pa0.z, pa0.w);
    s_rgH[2*RGN2 + tid] = make_uint2(pa1.x, pa1.y);
    s_rgH[3*RGN2 + tid] = make_uint2(pa1.z, pa1.w);
    s_rgH[0*RGN2 + tid + 256] = make_uint2(pb0.x, pb0.y);
    s_rgH[1*RGN2 + tid + 256] = make_uint2(pb0.z, pb0.w);
    s_rgH[2*RGN2 + tid + 256] = make_uint2(pb1.x, pb1.y);
    s_rgH[3*RGN2 + tid + 256] = make_uint2(pb1.z, pb1.w);
    if (tid + 512 < RGN2){
        size_t g2 = (size_t)s_goff[tid+512]*2;
        uint4 c0 = b2p[g2], c1v = b2p[g2+1];
        s_rgH[0*RGN2 + tid + 512] = make_uint2(c0.x, c0.y);
        s_rgH[1*RGN2 + tid + 512] = make_uint2(c0.z, c0.w);
        s_rgH[2*RGN2 + tid + 512] = make_uint2(c1v.x, c1v.y);
        s_rgH[3*RGN2 + tid + 512] = make_uint2(c1v.z, c1v.w);
    }
    for (int i=tid; i<KSEL*49; i+=NT){
        int k = i/49, p = i - 49*k;
        int c = s_cid[k];
        int pa = p/7, pb = p - 7*pa;
        s_off[k*49 + p] = s_ro[(c/WS)*7 + pa]*RGN + s_co[(c%WS)*7 + pb];
    }
    __syncthreads();

    // ---- aggregation: 196 threads, per-k: LDS.32 off + LDS.64 fp16 gather
    if (tid < 196){
        int p   = tid % 49;
        int cig = tid / 49;
        const uint2* rg = s_rgH + cig*RGN2;
        float a0=0.f, a1=0.f, a2=0.f, a3=0.f;
        #pragma unroll 2
        for (int k=0; k<KSEL; k+=4){
            float4 w4 = *(const float4*)(s_w + k);
            #pragma unroll
            for (int u=0; u<4; u++){
                float w = (u==0)?w4.x:(u==1)?w4.y:(u==2)?w4.z:w4.w;
                int off = s_off[(k+u)*49 + p];
                uint2 v = rg[off];
                float2 f0 = __half22float2(u2h(v.x));
                float2 f1 = __half22float2(u2h(v.y));
                a0 += w*f0.x; a1 += w*f0.y; a2 += w*f1.x; a3 += w*f1.y;
            }
        }
        int pa = p/7, pb = p - 7*pa;
        int pix = min(qi+pa,95)*WW + min(qj+pb,95);
        float* accb = g_acc + (size_t)(t*CI + cig*4)*HW + pix;
        atomicAdd(accb,        a0);
        atomicAdd(accb +   HW, a1);
        atomicAdd(accb + 2*HW, a2);
        atomicAdd(accb + 3*HW, a3);
    }
}

// ---------------------------------------------------------------- final: 2 pixels/thread, 128-thr blocks, 2-way co split
// grid = 2*144 blocks; 256-pixel chunk per block
__global__ void __launch_bounds__(NTC) k_final(const float* __restrict__ vid, const float* __restrict__ Ww,
                        const float* __restrict__ Wb, float* __restrict__ out){
    __shared__ __align__(16) float sw[C_*CI + C_];
    for (int i=threadIdx.x; i<C_*CI; i+=NTC) sw[i] = Ww[i];
    if (threadIdx.x < C_) sw[C_*CI+threadIdx.x] = Wb[threadIdx.x];
    __syncthreads();

    int sub  = blockIdx.x / 144;                // co range [32*sub, 32*sub+32)
    int base = (blockIdx.x % 144)*256 + threadIdx.x;
    int t = base / HW, pix = base % HW;

    // analytic overlap counts for both pixels
    float inv0, inv1;
    #pragma unroll
    for (int pp=0; pp<2; pp++){
        int px = pix + pp*128;
        int row = px / WW, col = px - row*WW;
        int cr = 0, cc = 0;
        #pragma unroll
        for (int a=0;a<7;a++){
            int v = row - a; cr += (v >= 0 && v <= 92 && (v & 3) == 0);
            int u = col - a; cc += (u >= 0 && u <= 92 && (u & 3) == 0);
        }
        if (row == 95) cr += 3;
        if (col == 95) cc += 3;
        float inv = 1.f / (float)(cr*cc);
        if (pp == 0) inv0 = inv; else inv1 = inv;
    }

    float y0[CI], y1[CI];
    #pragma unroll
    for (int ci=0;ci<CI;ci++){
        y0[ci] = g_acc[(t*CI+ci)*HW + pix]       * inv0;
        y1[ci] = g_acc[(t*CI+ci)*HW + pix + 128] * inv1;
    }

    const float* vp = vid + (size_t)t*C_*HW + pix;
    float*       op = out + (size_t)t*C_*HW + pix;
    int co0 = sub*32;
    #pragma unroll 4
    for (int u=0; u<32; u++){
        int co = co0 + u;
        float bias = sw[C_*CI+co];
        float s0 = bias, s1 = bias;
        #pragma unroll
        for (int g=0; g<4; g++){
            float4 w4 = *(const float4*)(sw + co*CI + 4*g);
            s0 += w4.x*y0[4*g] + w4.y*y0[4*g+1] + w4.z*y0[4*g+2] + w4.w*y0[4*g+3];
            s1 += w4.x*y1[4*g] + w4.y*y1[4*g+1] + w4.z*y1[4*g+2] + w4.w*y1[4*g+3];
        }
        op[co*HW]       = vp[co*HW]       + s0;
        op[co*HW + 128] = vp[co*HW + 128] + s1;
    }
}

// ---------------------------------------------------------------- launch
extern "C" void kernel_launch(void* const* d_in, const int* in_sizes, int n_in,
                              void* d_out, int out_size){
    const float* vid  = (const float*)d_in[0];
    const float* g_w  = (const float*)d_in[1];
    const float* g_b  = (const float*)d_in[2];
    const float* th_w = (const float*)d_in[3];
    const float* th_b = (const float*)d_in[4];
    const float* ph_w = (const float*)d_in[5];
    const float* ph_b = (const float*)d_in[6];
    const float* W_w  = (const float*)d_in[7];
    const float* W_b  = (const float*)d_in[8];
    float* out = (float*)d_out;

    const int SMEM = SM_TOT * 4;   // 75132 B
    cudaFuncSetAttribute(k_score, cudaFuncAttributeMaxDynamicSharedMemorySize, SMEM);

    k_proj  <<<4*144, NTC>>>(vid, g_w, g_b, th_w, th_b, ph_w, ph_b);
    k_score <<<T_*NQ, NT, SMEM>>>();
    k_final <<<2*144, NTC>>>(vid, W_w, W_b, out);
}